// round 1
// baseline (speedup 1.0000x reference)
#include <cuda_runtime.h>
#include <math.h>

#define B_ 2
#define N_ 2048
#define C_ 512
#define H_ 8
#define D_ 64
#define F3 (3*C_)          // 1536
#define SCALE 0.125f       // D^-0.5

// Scratch (device globals: allocation-free per harness rules)
__device__ float g_qkv[(size_t)B_*N_*F3];   // (b*N+n, 1536): [q|k|v] each h*64+d
__device__ float g_o  [(size_t)B_*N_*C_];   // (b,h,n,d) contiguous -> read as (4096,512)

// ---------------------------------------------------------------------------
// Generic tiled GEMM: C = A(MxK) * B(KxNc) [+ bias], all row-major fp32.
// 64x64 tile, BK=16, 256 threads, 4x4 micro-tile per thread.
// ---------------------------------------------------------------------------
__global__ void gemm64(const float* __restrict__ A, const float* __restrict__ Bm,
                       const float* __restrict__ bias, float* __restrict__ Cout,
                       int M, int Nc, int K)
{
    __shared__ float As[64][17];   // +1 pad: conflict-free a-broadcast
    __shared__ float Bs[16][64];
    const int tx = threadIdx.x & 15, ty = threadIdx.x >> 4;
    const int row0 = blockIdx.y * 64, col0 = blockIdx.x * 64;
    float acc[4][4] = {};

    for (int k0 = 0; k0 < K; k0 += 16) {
        {   // load A tile: 64x16, one float4 per thread
            int r = threadIdx.x >> 2, c4 = (threadIdx.x & 3) * 4;
            float4 v = *(const float4*)&A[(size_t)(row0 + r) * K + k0 + c4];
            As[r][c4] = v.x; As[r][c4+1] = v.y; As[r][c4+2] = v.z; As[r][c4+3] = v.w;
        }
        {   // load B tile: 16x64, one float4 per thread
            int r = threadIdx.x >> 4, c4 = (threadIdx.x & 15) * 4;
            *(float4*)&Bs[r][c4] = *(const float4*)&Bm[(size_t)(k0 + r) * Nc + col0 + c4];
        }
        __syncthreads();
        #pragma unroll
        for (int kk = 0; kk < 16; kk++) {
            float a[4];
            float4 bv = *(const float4*)&Bs[kk][tx * 4];
            #pragma unroll
            for (int i = 0; i < 4; i++) a[i] = As[ty * 4 + i][kk];
            #pragma unroll
            for (int i = 0; i < 4; i++) {
                acc[i][0] += a[i] * bv.x; acc[i][1] += a[i] * bv.y;
                acc[i][2] += a[i] * bv.z; acc[i][3] += a[i] * bv.w;
            }
        }
        __syncthreads();
    }
    #pragma unroll
    for (int i = 0; i < 4; i++) {
        int r = row0 + ty * 4 + i;
        int c = col0 + tx * 4;
        float4 v = make_float4(acc[i][0], acc[i][1], acc[i][2], acc[i][3]);
        if (bias) { v.x += bias[c]; v.y += bias[c+1]; v.z += bias[c+2]; v.w += bias[c+3]; }
        *(float4*)&Cout[(size_t)r * Nc + c] = v;
    }
}

// ---------------------------------------------------------------------------
// Flash attention, fp32. One block = (bh, 64 query rows). 256 threads.
// Online softmax; V stored transposed in smem so both inner GEMMs read
// contiguous float4s.
// ---------------------------------------------------------------------------
#define PAD 68                                  // floats per smem row (16B aligned)
#define ATTN_SMEM_BYTES ((4*64*PAD + 3*64) * 4) // 70400 bytes

__global__ void attn64(const float* __restrict__ qkv, float* __restrict__ O)
{
    extern __shared__ float sm[];
    float* Qs  = sm;                 // [64][PAD]  Q (pre-scaled)
    float* Ks  = Qs + 64 * PAD;      // [64][PAD]  K (seq, d)
    float* Vt  = Ks + 64 * PAD;      // [64][PAD]  V transposed (d, seq)
    float* Ss  = Vt + 64 * PAD;      // [64][PAD]  scores / P
    float* m_s = Ss + 64 * PAD;      // [64]
    float* l_s = m_s + 64;           // [64]
    float* a_s = l_s + 64;           // [64]

    const int tx = threadIdx.x & 15, ty = threadIdx.x >> 4;
    const int bh = blockIdx.y, b = bh >> 3, h = bh & 7;
    const int q0 = blockIdx.x * 64;
    const float* qb = qkv + (size_t)b * N_ * F3 + h * 64;
    const float* kb = qb + C_;
    const float* vb = qb + 2 * C_;

    // Load Q tile (pre-scaled by SCALE)
    #pragma unroll
    for (int it = 0; it < 4; it++) {
        int idx = threadIdx.x + it * 256;
        int r = idx >> 4, c4 = (idx & 15) * 4;
        float4 v = *(const float4*)&qb[(size_t)(q0 + r) * F3 + c4];
        float* dst = &Qs[r * PAD + c4];
        dst[0] = v.x * SCALE; dst[1] = v.y * SCALE;
        dst[2] = v.z * SCALE; dst[3] = v.w * SCALE;
    }
    if (threadIdx.x < 64) { m_s[threadIdx.x] = -INFINITY; l_s[threadIdx.x] = 0.f; }

    float acc[4][4] = {};

    for (int j0 = 0; j0 < N_; j0 += 64) {
        __syncthreads();   // Ks/Vt/Ss reuse barrier (covers first-iter Q/m/l too)
        // Load K tile + V tile (transposed)
        #pragma unroll
        for (int it = 0; it < 4; it++) {
            int idx = threadIdx.x + it * 256;
            int r = idx >> 4, c4 = (idx & 15) * 4;
            float4 kv = *(const float4*)&kb[(size_t)(j0 + r) * F3 + c4];
            float* kd = &Ks[r * PAD + c4];
            kd[0] = kv.x; kd[1] = kv.y; kd[2] = kv.z; kd[3] = kv.w;
            float4 vv = *(const float4*)&vb[(size_t)(j0 + r) * F3 + c4];
            Vt[(c4 + 0) * PAD + r] = vv.x;
            Vt[(c4 + 1) * PAD + r] = vv.y;
            Vt[(c4 + 2) * PAD + r] = vv.z;
            Vt[(c4 + 3) * PAD + r] = vv.w;
        }
        __syncthreads();

        // S = Q * K^T (both contiguous over d)
        float s[4][4] = {};
        #pragma unroll
        for (int kk = 0; kk < 64; kk += 4) {
            float4 qv[4], kvv[4];
            #pragma unroll
            for (int i = 0; i < 4; i++) qv[i]  = *(const float4*)&Qs[(ty*4 + i) * PAD + kk];
            #pragma unroll
            for (int j = 0; j < 4; j++) kvv[j] = *(const float4*)&Ks[(tx*4 + j) * PAD + kk];
            #pragma unroll
            for (int i = 0; i < 4; i++)
                #pragma unroll
                for (int j = 0; j < 4; j++)
                    s[i][j] += qv[i].x*kvv[j].x + qv[i].y*kvv[j].y
                             + qv[i].z*kvv[j].z + qv[i].w*kvv[j].w;
        }
        #pragma unroll
        for (int i = 0; i < 4; i++)
            *(float4*)&Ss[(ty*4 + i) * PAD + tx*4] =
                make_float4(s[i][0], s[i][1], s[i][2], s[i][3]);
        __syncthreads();

        // Online softmax: warp w owns rows [w*8, w*8+8)
        {
            int warp = threadIdx.x >> 5, lane = threadIdx.x & 31;
            #pragma unroll
            for (int rr = 0; rr < 8; rr++) {
                int r = warp * 8 + rr;
                float v0 = Ss[r * PAD + lane], v1 = Ss[r * PAD + lane + 32];
                float mx = fmaxf(v0, v1);
                #pragma unroll
                for (int o = 16; o > 0; o >>= 1)
                    mx = fmaxf(mx, __shfl_xor_sync(0xffffffffu, mx, o));
                float m_old = m_s[r];
                float m_new = fmaxf(m_old, mx);
                float p0 = __expf(v0 - m_new), p1 = __expf(v1 - m_new);
                Ss[r * PAD + lane] = p0; Ss[r * PAD + lane + 32] = p1;
                float sum = p0 + p1;
                #pragma unroll
                for (int o = 16; o > 0; o >>= 1)
                    sum += __shfl_xor_sync(0xffffffffu, sum, o);
                if (lane == 0) {
                    float al = __expf(m_old - m_new);   // == 0 on first tile
                    a_s[r] = al;
                    l_s[r] = l_s[r] * al + sum;
                    m_s[r] = m_new;
                }
            }
        }
        __syncthreads();

        // Rescale + O += P * V  (Vt is (d, seq) so both reads are contiguous)
        float al[4];
        #pragma unroll
        for (int i = 0; i < 4; i++) al[i] = a_s[ty*4 + i];
        #pragma unroll
        for (int i = 0; i < 4; i++)
            #pragma unroll
            for (int j = 0; j < 4; j++) acc[i][j] *= al[i];

        #pragma unroll
        for (int kk = 0; kk < 64; kk += 4) {
            float4 pv[4], vv[4];
            #pragma unroll
            for (int i = 0; i < 4; i++) pv[i] = *(const float4*)&Ss[(ty*4 + i) * PAD + kk];
            #pragma unroll
            for (int j = 0; j < 4; j++) vv[j] = *(const float4*)&Vt[(tx*4 + j) * PAD + kk];
            #pragma unroll
            for (int i = 0; i < 4; i++)
                #pragma unroll
                for (int j = 0; j < 4; j++)
                    acc[i][j] += pv[i].x*vv[j].x + pv[i].y*vv[j].y
                               + pv[i].z*vv[j].z + pv[i].w*vv[j].w;
        }
    }

    // Epilogue: divide by l, write O in (b,h,n,d) layout
    float* ob = O + ((size_t)(b * H_ + h) * N_ + q0) * D_;
    #pragma unroll
    for (int i = 0; i < 4; i++) {
        int r = ty * 4 + i;
        float inv = 1.0f / l_s[r];
        float4 v = make_float4(acc[i][0]*inv, acc[i][1]*inv, acc[i][2]*inv, acc[i][3]*inv);
        *(float4*)&ob[(size_t)r * D_ + tx * 4] = v;
    }
}

// ---------------------------------------------------------------------------
extern "C" void kernel_launch(void* const* d_in, const int* in_sizes, int n_in,
                              void* d_out, int out_size)
{
    const float* x      = (const float*)d_in[0];
    const float* qkv_w  = (const float*)d_in[1];
    const float* proj_w = (const float*)d_in[2];
    const float* proj_b = (const float*)d_in[3];
    float* out = (float*)d_out;

    float *qkv_p, *o_p;
    cudaGetSymbolAddress((void**)&qkv_p, g_qkv);
    cudaGetSymbolAddress((void**)&o_p,   g_o);

    cudaFuncSetAttribute(attn64, cudaFuncAttributeMaxDynamicSharedMemorySize,
                         ATTN_SMEM_BYTES);

    // 1) QKV projection: (4096x512) @ (512x1536)
    dim3 g1(F3 / 64, (B_ * N_) / 64);
    gemm64<<<g1, 256>>>(x, qkv_w, nullptr, qkv_p, B_ * N_, F3, C_);

    // 2) Flash attention per (bh, q-tile)
    dim3 g2(N_ / 64, B_ * H_);
    attn64<<<g2, 256, ATTN_SMEM_BYTES>>>(qkv_p, o_p);

    // 3) Output projection (reads O as (4096,512) == reshape-without-transpose)
    dim3 g3(C_ / 64, (B_ * N_) / 64);
    gemm64<<<g3, 256>>>(o_p, proj_w, proj_b, out, B_ * N_, C_, C_);
}

// round 2
// speedup vs baseline: 2.5513x; 2.5513x over previous
#include <cuda_runtime.h>
#include <math.h>

#define B_ 2
#define N_ 2048
#define C_ 512
#define H_ 8
#define D_ 64
#define F3 1536
#define SCALE 0.125f

// Scratch (device globals: allocation-free per harness rules)
__device__ float g_qkv[(size_t)B_*N_*F3];   // (b*N+n, 1536)
__device__ float g_o  [(size_t)B_*N_*C_];   // (b,h,n,d) -> read as (4096,512)

// ---------------------------------------------------------------------------
// tf32 helpers
// ---------------------------------------------------------------------------
__device__ __forceinline__ unsigned f2tf(float x) {
    unsigned u; asm("cvt.rna.tf32.f32 %0, %1;" : "=r"(u) : "f"(x)); return u;
}
__device__ __forceinline__ void split_tf32(float x, unsigned &hi, unsigned &lo) {
    hi = f2tf(x);
    lo = f2tf(x - __uint_as_float(hi));
}
__device__ __forceinline__ void mma8(float c[4], const unsigned a[4], const unsigned b[2]) {
    asm volatile("mma.sync.aligned.m16n8k8.row.col.f32.tf32.tf32.f32 "
        "{%0,%1,%2,%3}, {%4,%5,%6,%7}, {%8,%9}, {%0,%1,%2,%3};\n"
        : "+f"(c[0]), "+f"(c[1]), "+f"(c[2]), "+f"(c[3])
        : "r"(a[0]), "r"(a[1]), "r"(a[2]), "r"(a[3]), "r"(b[0]), "r"(b[1]));
}
__device__ __forceinline__ void mma3(float c[4], const unsigned ah[4], const unsigned al[4],
                                     const unsigned bh[2], const unsigned bl[2]) {
    mma8(c, ah, bh);    // hi*hi
    mma8(c, ah, bl);    // hi*lo
    mma8(c, al, bh);    // lo*hi
}

// ---------------------------------------------------------------------------
// Tensor-core GEMM: C = A(MxK) @ B(KxNc) [+bias], fp32 in/out, 3xTF32 mma.
// Block tile 128x64, BK=32, 256 threads = 8 warps (4x2), warp tile 32x32.
// ---------------------------------------------------------------------------
#define GPA 36   // As pitch  (≡4 mod 32: conflict-free A-fragment reads)
#define GPB 72   // Bs pitch  (≡8 mod 32: conflict-free B-fragment reads)
__global__ void gemm_tc(const float* __restrict__ A, const float* __restrict__ Bm,
                        const float* __restrict__ bias, float* __restrict__ Cout,
                        int M, int Nc, int K)
{
    __shared__ float As[128 * GPA];
    __shared__ float Bs[32 * GPB];
    const int tid  = threadIdx.x;
    const int lane = tid & 31, warp = tid >> 5;
    const int wm = warp >> 1, wn = warp & 1;
    const int row0 = blockIdx.y * 128, col0 = blockIdx.x * 64;
    const int g = lane >> 2, c = lane & 3;

    float acc[2][4][4] = {};   // [mtile][ntile][c-frag]

    for (int k0 = 0; k0 < K; k0 += 32) {
        #pragma unroll
        for (int i = 0; i < 4; i++) {            // A: 128x32
            int r = (tid >> 3) + i * 32, c4 = (tid & 7) * 4;
            *(float4*)&As[r * GPA + c4] =
                *(const float4*)&A[(size_t)(row0 + r) * K + k0 + c4];
        }
        #pragma unroll
        for (int i = 0; i < 2; i++) {            // B: 32x64
            int r = (tid >> 4) + i * 16, c4 = (tid & 15) * 4;
            *(float4*)&Bs[r * GPB + c4] =
                *(const float4*)&Bm[(size_t)(k0 + r) * Nc + col0 + c4];
        }
        __syncthreads();
        #pragma unroll
        for (int ks = 0; ks < 4; ks++) {
            unsigned ah[2][4], al[2][4];
            #pragma unroll
            for (int mt = 0; mt < 2; mt++) {
                int rb = wm * 32 + mt * 16;
                split_tf32(As[(rb + g    ) * GPA + ks*8 + c    ], ah[mt][0], al[mt][0]);
                split_tf32(As[(rb + g + 8) * GPA + ks*8 + c    ], ah[mt][1], al[mt][1]);
                split_tf32(As[(rb + g    ) * GPA + ks*8 + c + 4], ah[mt][2], al[mt][2]);
                split_tf32(As[(rb + g + 8) * GPA + ks*8 + c + 4], ah[mt][3], al[mt][3]);
            }
            #pragma unroll
            for (int nt = 0; nt < 4; nt++) {
                int col = wn * 32 + nt * 8 + g;
                unsigned bh2[2], bl2[2];
                split_tf32(Bs[(ks*8 + c    ) * GPB + col], bh2[0], bl2[0]);
                split_tf32(Bs[(ks*8 + c + 4) * GPB + col], bh2[1], bl2[1]);
                mma3(acc[0][nt], ah[0], al[0], bh2, bl2);
                mma3(acc[1][nt], ah[1], al[1], bh2, bl2);
            }
        }
        __syncthreads();
    }
    #pragma unroll
    for (int mt = 0; mt < 2; mt++)
        #pragma unroll
        for (int nt = 0; nt < 4; nt++) {
            int r  = row0 + wm * 32 + mt * 16 + g;
            int cc = col0 + wn * 32 + nt * 8 + 2 * c;
            float b0 = bias ? bias[cc] : 0.f, b1 = bias ? bias[cc + 1] : 0.f;
            *(float2*)&Cout[(size_t)r * Nc + cc] =
                make_float2(acc[mt][nt][0] + b0, acc[mt][nt][1] + b1);
            *(float2*)&Cout[(size_t)(r + 8) * Nc + cc] =
                make_float2(acc[mt][nt][2] + b0, acc[mt][nt][3] + b1);
        }
}

// ---------------------------------------------------------------------------
// Flash attention, 3xTF32 mma. Block = (bh, 64 Q rows), 128 threads = 4 warps,
// each warp owns 16 Q rows. KV tile 64. No smem transposes needed: B-fragment
// of S=Q*K^T reads natural K[j][d]; B-fragment of P*V reads natural V[j][d].
// ---------------------------------------------------------------------------
#define APQ 68   // Qs/Ps pitch (A-pattern + S B-pattern: ≡4 mod 32)
#define APV 72   // Vs pitch    (PV B-pattern: ≡8 mod 32)
#define ATTN_SMEM ((64*APQ*3 + 64*APV) * 4)   // Qs,Ks,Ps @68 + Vs @72 = 70656 B

__global__ void attn_tc(const float* __restrict__ qkv, float* __restrict__ O)
{
    extern __shared__ float sm[];
    float* Qs = sm;                 // [64][APQ] Q (pre-scaled)
    float* Ks = Qs + 64 * APQ;      // [64][APQ] K natural (j, d)
    float* Ps = Ks + 64 * APQ;      // [64][APQ] P
    float* Vs = Ps + 64 * APQ;      // [64][APV] V natural (j, d)

    const int tid  = threadIdx.x;   // 128
    const int lane = tid & 31, warp = tid >> 5;
    const int g = lane >> 2, c = lane & 3;
    const int bh = blockIdx.y, b = bh >> 3, h = bh & 7;
    const int q0 = blockIdx.x * 64;
    const float* qb = qkv + (size_t)b * N_ * F3 + h * 64;
    const float* kb = qb + C_;
    const float* vb = qb + 2 * C_;

    #pragma unroll
    for (int i = 0; i < 8; i++) {               // load Q (scaled)
        int idx = tid + i * 128;
        int r = idx >> 4, c4 = (idx & 15) * 4;
        float4 v = *(const float4*)&qb[(size_t)(q0 + r) * F3 + c4];
        v.x *= SCALE; v.y *= SCALE; v.z *= SCALE; v.w *= SCALE;
        *(float4*)&Qs[r * APQ + c4] = v;
    }

    float m0 = -INFINITY, m1 = -INFINITY, l0 = 0.f, l1 = 0.f;
    float acc[8][4] = {};                        // O fragments: 8 d-tiles

    for (int j0 = 0; j0 < N_; j0 += 64) {
        __syncthreads();
        #pragma unroll
        for (int i = 0; i < 8; i++) {            // load K, V (natural layout)
            int idx = tid + i * 128;
            int r = idx >> 4, c4 = (idx & 15) * 4;
            *(float4*)&Ks[r * APQ + c4] = *(const float4*)&kb[(size_t)(j0 + r) * F3 + c4];
            *(float4*)&Vs[r * APV + c4] = *(const float4*)&vb[(size_t)(j0 + r) * F3 + c4];
        }
        __syncthreads();

        // ---- S = Q @ K^T : warp rows [warp*16, warp*16+16), all 64 j cols
        float sf[8][4] = {};
        const int rb = warp * 16;
        #pragma unroll
        for (int ks = 0; ks < 8; ks++) {
            unsigned ah[4], al[4];
            split_tf32(Qs[(rb + g    ) * APQ + ks*8 + c    ], ah[0], al[0]);
            split_tf32(Qs[(rb + g + 8) * APQ + ks*8 + c    ], ah[1], al[1]);
            split_tf32(Qs[(rb + g    ) * APQ + ks*8 + c + 4], ah[2], al[2]);
            split_tf32(Qs[(rb + g + 8) * APQ + ks*8 + c + 4], ah[3], al[3]);
            #pragma unroll
            for (int nt = 0; nt < 8; nt++) {
                unsigned bh2[2], bl2[2];          // B(k=d, n=j) = K[j][d]
                split_tf32(Ks[(nt*8 + g) * APQ + ks*8 + c    ], bh2[0], bl2[0]);
                split_tf32(Ks[(nt*8 + g) * APQ + ks*8 + c + 4], bh2[1], bl2[1]);
                mma3(sf[nt], ah, al, bh2, bl2);
            }
        }

        // ---- online softmax (rows g / g+8, owned by quads)
        float mx0 = -INFINITY, mx1 = -INFINITY;
        #pragma unroll
        for (int nt = 0; nt < 8; nt++) {
            mx0 = fmaxf(mx0, fmaxf(sf[nt][0], sf[nt][1]));
            mx1 = fmaxf(mx1, fmaxf(sf[nt][2], sf[nt][3]));
        }
        mx0 = fmaxf(mx0, __shfl_xor_sync(~0u, mx0, 1));
        mx0 = fmaxf(mx0, __shfl_xor_sync(~0u, mx0, 2));
        mx1 = fmaxf(mx1, __shfl_xor_sync(~0u, mx1, 1));
        mx1 = fmaxf(mx1, __shfl_xor_sync(~0u, mx1, 2));
        float m0n = fmaxf(m0, mx0), m1n = fmaxf(m1, mx1);
        float al0 = __expf(m0 - m0n), al1 = __expf(m1 - m1n);  // 0 on first tile
        float s0 = 0.f, s1 = 0.f;
        #pragma unroll
        for (int nt = 0; nt < 8; nt++) {
            sf[nt][0] = __expf(sf[nt][0] - m0n);
            sf[nt][1] = __expf(sf[nt][1] - m0n);
            sf[nt][2] = __expf(sf[nt][2] - m1n);
            sf[nt][3] = __expf(sf[nt][3] - m1n);
            s0 += sf[nt][0] + sf[nt][1];
            s1 += sf[nt][2] + sf[nt][3];
        }
        s0 += __shfl_xor_sync(~0u, s0, 1); s0 += __shfl_xor_sync(~0u, s0, 2);
        s1 += __shfl_xor_sync(~0u, s1, 1); s1 += __shfl_xor_sync(~0u, s1, 2);
        l0 = l0 * al0 + s0;  l1 = l1 * al1 + s1;
        m0 = m0n;            m1 = m1n;

        #pragma unroll
        for (int nt = 0; nt < 8; nt++) {          // rescale running O
            acc[nt][0] *= al0; acc[nt][1] *= al0;
            acc[nt][2] *= al1; acc[nt][3] *= al1;
        }

        // ---- stage P (warp-private rows, warp-local sync only)
        #pragma unroll
        for (int nt = 0; nt < 8; nt++) {
            *(float2*)&Ps[(rb + g    ) * APQ + nt*8 + 2*c] = make_float2(sf[nt][0], sf[nt][1]);
            *(float2*)&Ps[(rb + g + 8) * APQ + nt*8 + 2*c] = make_float2(sf[nt][2], sf[nt][3]);
        }
        __syncwarp();

        // ---- O += P @ V
        #pragma unroll
        for (int ks = 0; ks < 8; ks++) {
            unsigned ah[4], al[4];
            split_tf32(Ps[(rb + g    ) * APQ + ks*8 + c    ], ah[0], al[0]);
            split_tf32(Ps[(rb + g + 8) * APQ + ks*8 + c    ], ah[1], al[1]);
            split_tf32(Ps[(rb + g    ) * APQ + ks*8 + c + 4], ah[2], al[2]);
            split_tf32(Ps[(rb + g + 8) * APQ + ks*8 + c + 4], ah[3], al[3]);
            #pragma unroll
            for (int nt = 0; nt < 8; nt++) {
                unsigned bh2[2], bl2[2];          // B(k=j, n=d) = V[j][d]
                split_tf32(Vs[(ks*8 + c    ) * APV + nt*8 + g], bh2[0], bl2[0]);
                split_tf32(Vs[(ks*8 + c + 4) * APV + nt*8 + g], bh2[1], bl2[1]);
                mma3(acc[nt], ah, al, bh2, bl2);
            }
        }
    }

    // ---- epilogue: /l, write O in (b,h,n,d) layout
    float i0 = 1.f / l0, i1 = 1.f / l1;
    float* ob = O + ((size_t)(b * H_ + h) * N_ + q0 + warp * 16) * D_;
    #pragma unroll
    for (int nt = 0; nt < 8; nt++) {
        int cc = nt * 8 + 2 * c;
        *(float2*)&ob[(size_t)g * D_ + cc]       = make_float2(acc[nt][0]*i0, acc[nt][1]*i0);
        *(float2*)&ob[(size_t)(g + 8) * D_ + cc] = make_float2(acc[nt][2]*i1, acc[nt][3]*i1);
    }
}

// ---------------------------------------------------------------------------
extern "C" void kernel_launch(void* const* d_in, const int* in_sizes, int n_in,
                              void* d_out, int out_size)
{
    const float* x      = (const float*)d_in[0];
    const float* qkv_w  = (const float*)d_in[1];
    const float* proj_w = (const float*)d_in[2];
    const float* proj_b = (const float*)d_in[3];
    float* out = (float*)d_out;

    float *qkv_p, *o_p;
    cudaGetSymbolAddress((void**)&qkv_p, g_qkv);
    cudaGetSymbolAddress((void**)&o_p,   g_o);

    cudaFuncSetAttribute(attn_tc, cudaFuncAttributeMaxDynamicSharedMemorySize,
                         ATTN_SMEM);

    // 1) QKV projection: (4096x512) @ (512x1536)
    dim3 g1(F3 / 64, (B_ * N_) / 128);
    gemm_tc<<<g1, 256>>>(x, qkv_w, nullptr, qkv_p, B_ * N_, F3, C_);

    // 2) Flash attention per (bh, q-tile)
    dim3 g2(N_ / 64, B_ * H_);
    attn_tc<<<g2, 128, ATTN_SMEM>>>(qkv_p, o_p);

    // 3) Output projection (reads O as (4096,512) == reshape-without-transpose)
    dim3 g3(C_ / 64, (B_ * N_) / 128);
    gemm_tc<<<g3, 256>>>(o_p, proj_w, proj_b, out, B_ * N_, C_, C_);
}

// round 4
// speedup vs baseline: 4.3572x; 1.7079x over previous
#include <cuda_runtime.h>
#include <cuda_bf16.h>
#include <math.h>

#define B_ 2
#define N_ 2048
#define C_ 512
#define H_ 8
#define D_ 64
#define F3 1536
#define SCALE 0.125f

// Scratch (device globals: allocation-free per harness rules)
__device__ float g_qkv[(size_t)B_*N_*F3];   // (b*N+n, 1536)
__device__ float g_o  [(size_t)B_*N_*C_];   // (b,h,n,d) -> read as (4096,512)

// ---------------------------------------------------------------------------
// bf16 split helpers: x ~= hi + lo, each bf16. Pairwise packed (low 16 = first).
// ---------------------------------------------------------------------------
__device__ __forceinline__ void split2(float x, float y, unsigned &hi, unsigned &lo) {
    __nv_bfloat162 h = __floats2bfloat162_rn(x, y);
    float hx = __bfloat162float(h.x), hy = __bfloat162float(h.y);
    __nv_bfloat162 l = __floats2bfloat162_rn(x - hx, y - hy);
    hi = *reinterpret_cast<const unsigned*>(&h);
    lo = *reinterpret_cast<const unsigned*>(&l);
}
__device__ __forceinline__ void mma16(float c[4], const unsigned a[4], const unsigned b[2]) {
    asm volatile("mma.sync.aligned.m16n8k16.row.col.f32.bf16.bf16.f32 "
        "{%0,%1,%2,%3}, {%4,%5,%6,%7}, {%8,%9}, {%0,%1,%2,%3};\n"
        : "+f"(c[0]), "+f"(c[1]), "+f"(c[2]), "+f"(c[3])
        : "r"(a[0]), "r"(a[1]), "r"(a[2]), "r"(a[3]), "r"(b[0]), "r"(b[1]));
}
__device__ __forceinline__ void mma3(float c[4], const unsigned ah[4], const unsigned al[4],
                                     const unsigned bh[2], const unsigned bl[2]) {
    mma16(c, ah, bh);   // hi*hi
    mma16(c, ah, bl);   // hi*lo
    mma16(c, al, bh);   // lo*hi
}

// ---------------------------------------------------------------------------
// GEMM: C = A(MxK) @ B(KxNc) [+bias], fp32 in/out, 3xBF16 mma m16n8k16.
// Block 128x64, BK=32, 256 thr = 8 warps (4x2), warp tile 32x32.
// Smem holds PRE-SPLIT {hi-pair, lo-pair} uint2 per k-pair.
// ---------------------------------------------------------------------------
#define APG 20   // As pitch (uint2 units), >=16, ==4 mod 16
#define BPG 68   // Bs pitch (uint2 units), >=64, ==4 mod 16
__global__ void gemm_bf3(const float* __restrict__ A, const float* __restrict__ Bm,
                         const float* __restrict__ bias, float* __restrict__ Cout,
                         int M, int Nc, int K)
{
    __shared__ uint2 As[128 * APG];   // [row][kpair]
    __shared__ uint2 Bs[16 * BPG];    // [kpair][col]
    const int tid = threadIdx.x, lane = tid & 31, warp = tid >> 5;
    const int wm = warp >> 1, wn = warp & 1;
    const int row0 = blockIdx.y * 128, col0 = blockIdx.x * 64;
    const int g = lane >> 2, c = lane & 3;

    float acc[2][4][4] = {};

    for (int k0 = 0; k0 < K; k0 += 32) {
        #pragma unroll
        for (int i = 0; i < 4; i++) {                 // A: 128x32, pairs along k
            int idx = tid + i * 256;
            int r = idx >> 3, c4 = (idx & 7) * 4;
            float4 v = *(const float4*)&A[(size_t)(row0 + r) * K + k0 + c4];
            unsigned h0, l0h, h1, l1h;
            split2(v.x, v.y, h0, l0h);
            split2(v.z, v.w, h1, l1h);
            *(uint4*)&As[r * APG + (c4 >> 1)] = make_uint4(h0, l0h, h1, l1h);
        }
        #pragma unroll
        for (int i = 0; i < 2; i++) {                 // B: 32x64, pairs along k (rows)
            int idx = tid + i * 256;
            int r = idx >> 4, c4 = (idx & 15) * 4;
            float4 v = *(const float4*)&Bm[(size_t)(k0 + r) * Nc + col0 + c4];
            float ox = __shfl_xor_sync(~0u, v.x, 16);
            float oy = __shfl_xor_sync(~0u, v.y, 16);
            float oz = __shfl_xor_sync(~0u, v.z, 16);
            float ow = __shfl_xor_sync(~0u, v.w, 16);
            if (lane < 16) {                          // even row: pair (r, r+1)
                int p = r >> 1;
                unsigned h0,l0h,h1,l1h,h2,l2h,h3,l3h;
                split2(v.x, ox, h0, l0h);  split2(v.y, oy, h1, l1h);
                split2(v.z, oz, h2, l2h);  split2(v.w, ow, h3, l3h);
                *(uint4*)&Bs[p * BPG + c4]     = make_uint4(h0, l0h, h1, l1h);
                *(uint4*)&Bs[p * BPG + c4 + 2] = make_uint4(h2, l2h, h3, l3h);
            }
        }
        __syncthreads();

        #pragma unroll
        for (int ks = 0; ks < 2; ks++) {
            unsigned ah[2][4], al[2][4];
            #pragma unroll
            for (int mt = 0; mt < 2; mt++) {
                int rb = wm * 32 + mt * 16;
                uint2 t;
                t = As[(rb + g    ) * APG + ks*8 + c    ]; ah[mt][0]=t.x; al[mt][0]=t.y;
                t = As[(rb + g + 8) * APG + ks*8 + c    ]; ah[mt][1]=t.x; al[mt][1]=t.y;
                t = As[(rb + g    ) * APG + ks*8 + c + 4]; ah[mt][2]=t.x; al[mt][2]=t.y;
                t = As[(rb + g + 8) * APG + ks*8 + c + 4]; ah[mt][3]=t.x; al[mt][3]=t.y;
            }
            #pragma unroll
            for (int nt = 0; nt < 4; nt++) {
                int n = wn * 32 + nt * 8 + g;
                uint2 t0 = Bs[(ks*8 + c    ) * BPG + n];
                uint2 t1 = Bs[(ks*8 + c + 4) * BPG + n];
                unsigned bh2[2] = {t0.x, t1.x}, bl2[2] = {t0.y, t1.y};
                mma3(acc[0][nt], ah[0], al[0], bh2, bl2);
                mma3(acc[1][nt], ah[1], al[1], bh2, bl2);
            }
        }
        __syncthreads();
    }
    #pragma unroll
    for (int mt = 0; mt < 2; mt++)
        #pragma unroll
        for (int nt = 0; nt < 4; nt++) {
            int r  = row0 + wm * 32 + mt * 16 + g;
            int cc = col0 + wn * 32 + nt * 8 + 2 * c;
            float b0 = bias ? bias[cc] : 0.f, b1 = bias ? bias[cc + 1] : 0.f;
            *(float2*)&Cout[(size_t)r * Nc + cc] =
                make_float2(acc[mt][nt][0] + b0, acc[mt][nt][1] + b1);
            *(float2*)&Cout[(size_t)(r + 8) * Nc + cc] =
                make_float2(acc[mt][nt][2] + b0, acc[mt][nt][3] + b1);
        }
}

// ---------------------------------------------------------------------------
// Flash attention, 3xBF16 mma. Block = (bh, 128 Q rows), 256 thr = 8 warps,
// warp owns 16 Q rows. KV tile 64. Q fragments live in registers (split once).
// K pre-split pairs along d; V pre-split pairs along j (for PV B-fragments).
// P stays in registers: S-accumulator frags ARE the PV A-frags for m16n8k16.
// ---------------------------------------------------------------------------
#define KP 36    // Ks pitch (uint2), >=32, ==4 mod 16
#define VP 68    // Vs pitch (uint2), >=64, ==4 mod 16
#define QSP 68   // Q staging pitch (floats)
#define ATTN_SMEM_B ((64*KP + 32*VP) * 8)   // 35840 >= 128*QSP*4 = 34816

__global__ void attn_bf3(const float* __restrict__ qkv, float* __restrict__ O)
{
    __shared__ char smraw[ATTN_SMEM_B];
    float* qstage = (float*)smraw;            // [128][QSP] (prologue only)
    uint2* Ks = (uint2*)smraw;                // [64][KP]  {hi(d-pair), lo}
    uint2* Vs = Ks + 64 * KP;                 // [32][VP]  {hi(j-pair), lo} per d

    const int tid = threadIdx.x, lane = tid & 31, warp = tid >> 5;
    const int g = lane >> 2, c = lane & 3;
    const int rb = warp * 16;
    const int bh = blockIdx.y, b = bh >> 3, h = bh & 7;
    const int q0 = blockIdx.x * 128;
    const float* qb = qkv + (size_t)b * N_ * F3 + h * 64;
    const float* kb = qb + C_;
    const float* vb = qb + 2 * C_;

    // ---- prologue: stage Q (scaled), then split fragments into registers
    #pragma unroll
    for (int i = 0; i < 8; i++) {
        int idx = tid + i * 256;
        int r = idx >> 4, c4 = (idx & 15) * 4;
        float4 v = *(const float4*)&qb[(size_t)(q0 + r) * F3 + c4];
        v.x *= SCALE; v.y *= SCALE; v.z *= SCALE; v.w *= SCALE;
        *(float4*)&qstage[r * QSP + c4] = v;
    }
    __syncthreads();
    unsigned qh[4][4], ql[4][4];
    #pragma unroll
    for (int ks = 0; ks < 4; ks++) {
        float2 t0 = *(const float2*)&qstage[(rb + g    ) * QSP + ks*16 + 2*c    ];
        float2 t1 = *(const float2*)&qstage[(rb + g + 8) * QSP + ks*16 + 2*c    ];
        float2 t2 = *(const float2*)&qstage[(rb + g    ) * QSP + ks*16 + 2*c + 8];
        float2 t3 = *(const float2*)&qstage[(rb + g + 8) * QSP + ks*16 + 2*c + 8];
        split2(t0.x, t0.y, qh[ks][0], ql[ks][0]);
        split2(t1.x, t1.y, qh[ks][1], ql[ks][1]);
        split2(t2.x, t2.y, qh[ks][2], ql[ks][2]);
        split2(t3.x, t3.y, qh[ks][3], ql[ks][3]);
    }

    float m0 = -INFINITY, m1 = -INFINITY, l0 = 0.f, l1 = 0.f;
    float acc[8][4] = {};

    for (int j0 = 0; j0 < N_; j0 += 64) {
        __syncthreads();   // protects Ks/Vs reuse (and qstage on first iter)
        #pragma unroll
        for (int i = 0; i < 4; i++) {
            int idx = tid + i * 256;
            int r = idx >> 4, c4 = (idx & 15) * 4;
            // K: pairs along d (within this thread's float4)
            float4 kv = *(const float4*)&kb[(size_t)(j0 + r) * F3 + c4];
            unsigned h0,l0h,h1,l1h;
            split2(kv.x, kv.y, h0, l0h);
            split2(kv.z, kv.w, h1, l1h);
            *(uint4*)&Ks[r * KP + (c4 >> 1)] = make_uint4(h0, l0h, h1, l1h);
            // V: pairs along j (lane r pairs with lane^16 = row r^1)
            float4 vv = *(const float4*)&vb[(size_t)(j0 + r) * F3 + c4];
            float ox = __shfl_xor_sync(~0u, vv.x, 16);
            float oy = __shfl_xor_sync(~0u, vv.y, 16);
            float oz = __shfl_xor_sync(~0u, vv.z, 16);
            float ow = __shfl_xor_sync(~0u, vv.w, 16);
            if (lane < 16) {                          // even row
                int p = r >> 1;
                unsigned a0,b0,a1,b1,a2,b2,a3,b3;
                split2(vv.x, ox, a0, b0);  split2(vv.y, oy, a1, b1);
                split2(vv.z, oz, a2, b2);  split2(vv.w, ow, a3, b3);
                *(uint4*)&Vs[p * VP + c4]     = make_uint4(a0, b0, a1, b1);
                *(uint4*)&Vs[p * VP + c4 + 2] = make_uint4(a2, b2, a3, b3);
            }
        }
        __syncthreads();

        // ---- S = Q @ K^T (k-dim = d, 4 ksteps of 16)
        float sf[8][4] = {};
        #pragma unroll
        for (int ks = 0; ks < 4; ks++) {
            #pragma unroll
            for (int nt = 0; nt < 8; nt++) {
                uint2 t0 = Ks[(nt*8 + g) * KP + ks*8 + c    ];
                uint2 t1 = Ks[(nt*8 + g) * KP + ks*8 + c + 4];
                unsigned bh2[2] = {t0.x, t1.x}, bl2[2] = {t0.y, t1.y};
                mma3(sf[nt], qh[ks], ql[ks], bh2, bl2);
            }
        }

        // ---- online softmax (rows g / g+8, quad-reduced)
        float mx0 = -INFINITY, mx1 = -INFINITY;
        #pragma unroll
        for (int nt = 0; nt < 8; nt++) {
            mx0 = fmaxf(mx0, fmaxf(sf[nt][0], sf[nt][1]));
            mx1 = fmaxf(mx1, fmaxf(sf[nt][2], sf[nt][3]));
        }
        mx0 = fmaxf(mx0, __shfl_xor_sync(~0u, mx0, 1));
        mx0 = fmaxf(mx0, __shfl_xor_sync(~0u, mx0, 2));
        mx1 = fmaxf(mx1, __shfl_xor_sync(~0u, mx1, 1));
        mx1 = fmaxf(mx1, __shfl_xor_sync(~0u, mx1, 2));
        float m0n = fmaxf(m0, mx0), m1n = fmaxf(m1, mx1);
        float al0 = __expf(m0 - m0n), al1 = __expf(m1 - m1n);  // 0 on first tile
        float s0 = 0.f, s1 = 0.f;
        #pragma unroll
        for (int nt = 0; nt < 8; nt++) {
            sf[nt][0] = __expf(sf[nt][0] - m0n);
            sf[nt][1] = __expf(sf[nt][1] - m0n);
            sf[nt][2] = __expf(sf[nt][2] - m1n);
            sf[nt][3] = __expf(sf[nt][3] - m1n);
            s0 += sf[nt][0] + sf[nt][1];
            s1 += sf[nt][2] + sf[nt][3];
        }
        s0 += __shfl_xor_sync(~0u, s0, 1); s0 += __shfl_xor_sync(~0u, s0, 2);
        s1 += __shfl_xor_sync(~0u, s1, 1); s1 += __shfl_xor_sync(~0u, s1, 2);
        l0 = l0 * al0 + s0;  l1 = l1 * al1 + s1;
        m0 = m0n;            m1 = m1n;
        #pragma unroll
        for (int nt = 0; nt < 8; nt++) {
            acc[nt][0] *= al0; acc[nt][1] *= al0;
            acc[nt][2] *= al1; acc[nt][3] *= al1;
        }

        // ---- O += P @ V (k-dim = j; P frags built in-register from sf)
        #pragma unroll
        for (int ks = 0; ks < 4; ks++) {
            unsigned pah[4], pal[4];
            split2(sf[2*ks  ][0], sf[2*ks  ][1], pah[0], pal[0]);  // rows g,   j=16ks+2c
            split2(sf[2*ks  ][2], sf[2*ks  ][3], pah[1], pal[1]);  // rows g+8
            split2(sf[2*ks+1][0], sf[2*ks+1][1], pah[2], pal[2]);  // rows g,   j+8
            split2(sf[2*ks+1][2], sf[2*ks+1][3], pah[3], pal[3]);  // rows g+8
            #pragma unroll
            for (int nt = 0; nt < 8; nt++) {
                uint2 t0 = Vs[(ks*8 + c    ) * VP + nt*8 + g];
                uint2 t1 = Vs[(ks*8 + c + 4) * VP + nt*8 + g];
                unsigned bh2[2] = {t0.x, t1.x}, bl2[2] = {t0.y, t1.y};
                mma3(acc[nt], pah, pal, bh2, bl2);
            }
        }
    }

    // ---- epilogue: /l, write O in (b,h,n,d) layout
    float i0 = 1.f / l0, i1 = 1.f / l1;
    float* ob = O + ((size_t)(b * H_ + h) * N_ + q0 + rb) * D_;
    #pragma unroll
    for (int nt = 0; nt < 8; nt++) {
        int cc = nt * 8 + 2 * c;
        *(float2*)&ob[(size_t)g * D_ + cc]       = make_float2(acc[nt][0]*i0, acc[nt][1]*i0);
        *(float2*)&ob[(size_t)(g + 8) * D_ + cc] = make_float2(acc[nt][2]*i1, acc[nt][3]*i1);
    }
}

// ---------------------------------------------------------------------------
extern "C" void kernel_launch(void* const* d_in, const int* in_sizes, int n_in,
                              void* d_out, int out_size)
{
    const float* x      = (const float*)d_in[0];
    const float* qkv_w  = (const float*)d_in[1];
    const float* proj_w = (const float*)d_in[2];
    const float* proj_b = (const float*)d_in[3];
    float* out = (float*)d_out;

    float *qkv_p, *o_p;
    cudaGetSymbolAddress((void**)&qkv_p, g_qkv);
    cudaGetSymbolAddress((void**)&o_p,   g_o);

    // 1) QKV projection: (4096x512) @ (512x1536)
    dim3 g1(F3 / 64, (B_ * N_) / 128);
    gemm_bf3<<<g1, 256>>>(x, qkv_w, nullptr, qkv_p, B_ * N_, F3, C_);

    // 2) Flash attention per (bh, 128-row q-tile)
    dim3 g2(N_ / 128, B_ * H_);
    attn_bf3<<<g2, 256>>>(qkv_p, o_p);

    // 3) Output projection (reads O as (4096,512) == reshape-without-transpose)
    dim3 g3(C_ / 64, (B_ * N_) / 128);
    gemm_bf3<<<g3, 256>>>(o_p, proj_w, proj_b, out, B_ * N_, C_, C_);
}

// round 5
// speedup vs baseline: 5.5775x; 1.2801x over previous
#include <cuda_runtime.h>
#include <cuda_bf16.h>
#include <cuda_fp16.h>
#include <math.h>

#define B_ 2
#define N_ 2048
#define C_ 512
#define H_ 8
#define D_ 64
#define F3 1536
#define SCALE 0.125f

// Scratch (device globals: allocation-free per harness rules)
__device__ float g_qkv[(size_t)B_*N_*F3];   // (b*N+n, 1536)
__device__ float g_o  [(size_t)B_*N_*C_];   // (b,h,n,d) -> read as (4096,512)

// ---------------------------------------------------------------------------
// bf16 3-term helpers (kept for the exp-sensitive S = Q*K^T stage)
// ---------------------------------------------------------------------------
__device__ __forceinline__ void split2b(float x, float y, unsigned &hi, unsigned &lo) {
    __nv_bfloat162 h = __floats2bfloat162_rn(x, y);
    float hx = __bfloat162float(h.x), hy = __bfloat162float(h.y);
    __nv_bfloat162 l = __floats2bfloat162_rn(x - hx, y - hy);
    hi = *reinterpret_cast<const unsigned*>(&h);
    lo = *reinterpret_cast<const unsigned*>(&l);
}
__device__ __forceinline__ void mma16b(float c[4], const unsigned a[4], const unsigned b[2]) {
    asm volatile("mma.sync.aligned.m16n8k16.row.col.f32.bf16.bf16.f32 "
        "{%0,%1,%2,%3}, {%4,%5,%6,%7}, {%8,%9}, {%0,%1,%2,%3};\n"
        : "+f"(c[0]), "+f"(c[1]), "+f"(c[2]), "+f"(c[3])
        : "r"(a[0]), "r"(a[1]), "r"(a[2]), "r"(a[3]), "r"(b[0]), "r"(b[1]));
}
__device__ __forceinline__ void mma3b(float c[4], const unsigned ah[4], const unsigned al[4],
                                      const unsigned bh[2], const unsigned bl[2]) {
    mma16b(c, ah, bh);
    mma16b(c, ah, bl);
    mma16b(c, al, bh);
}

// ---------------------------------------------------------------------------
// fp16 2-term helpers: A split exactly (ah+al), B rounded once.
// c = ah*bh + al*bh ; error = a*(b-bh) ~ 2^-11 relative.
// ---------------------------------------------------------------------------
__device__ __forceinline__ void split2h(float x, float y, unsigned &hi, unsigned &lo) {
    __half2 h = __floats2half2_rn(x, y);
    float hx = __half2float(h.x), hy = __half2float(h.y);
    __half2 l = __floats2half2_rn(x - hx, y - hy);
    hi = *reinterpret_cast<const unsigned*>(&h);
    lo = *reinterpret_cast<const unsigned*>(&l);
}
__device__ __forceinline__ unsigned pack2h(float x, float y) {
    __half2 h = __floats2half2_rn(x, y);
    return *reinterpret_cast<const unsigned*>(&h);
}
__device__ __forceinline__ void mma16h(float c[4], const unsigned a[4], const unsigned b[2]) {
    asm volatile("mma.sync.aligned.m16n8k16.row.col.f32.f16.f16.f32 "
        "{%0,%1,%2,%3}, {%4,%5,%6,%7}, {%8,%9}, {%0,%1,%2,%3};\n"
        : "+f"(c[0]), "+f"(c[1]), "+f"(c[2]), "+f"(c[3])
        : "r"(a[0]), "r"(a[1]), "r"(a[2]), "r"(a[3]), "r"(b[0]), "r"(b[1]));
}
__device__ __forceinline__ void mma2h(float c[4], const unsigned ah[4], const unsigned al[4],
                                      const unsigned b[2]) {
    mma16h(c, ah, b);
    mma16h(c, al, b);
}

// ---------------------------------------------------------------------------
// GEMM: C = A(MxK) @ B(KxNc) [+bias], fp32 in/out, 2x FP16 mma m16n8k16.
// Block 128x64, BK=32, 256 thr = 8 warps (4x2), warp tile 32x32.
// As: pre-split {hi-pair, lo-pair} uint2 per k-pair. Bs: rounded half2 pairs.
// ---------------------------------------------------------------------------
#define APG 20   // As pitch (uint2 units), ==4 mod 16 -> conflict-free
#define BPN 72   // Bs pitch (unsigned units), ==8 mod 32 -> conflict-free
__global__ void gemm_h2(const float* __restrict__ A, const float* __restrict__ Bm,
                        const float* __restrict__ bias, float* __restrict__ Cout,
                        int M, int Nc, int K)
{
    __shared__ uint2    As[128 * APG];   // [row][kpair] {hi,lo}
    __shared__ unsigned Bs[16 * BPN];    // [kpair][col] hi only
    const int tid = threadIdx.x, lane = tid & 31, warp = tid >> 5;
    const int wm = warp >> 1, wn = warp & 1;
    const int row0 = blockIdx.y * 128, col0 = blockIdx.x * 64;
    const int g = lane >> 2, c = lane & 3;

    float acc[2][4][4] = {};

    for (int k0 = 0; k0 < K; k0 += 32) {
        #pragma unroll
        for (int i = 0; i < 4; i++) {                 // A: 128x32, split pairs along k
            int idx = tid + i * 256;
            int r = idx >> 3, c4 = (idx & 7) * 4;
            float4 v = *(const float4*)&A[(size_t)(row0 + r) * K + k0 + c4];
            unsigned h0, l0h, h1, l1h;
            split2h(v.x, v.y, h0, l0h);
            split2h(v.z, v.w, h1, l1h);
            *(uint4*)&As[r * APG + (c4 >> 1)] = make_uint4(h0, l0h, h1, l1h);
        }
        #pragma unroll
        for (int i = 0; i < 2; i++) {                 // B: 32x64, rounded pairs along k
            int idx = tid + i * 256;
            int r = idx >> 4, c4 = (idx & 15) * 4;
            float4 v = *(const float4*)&Bm[(size_t)(k0 + r) * Nc + col0 + c4];
            float ox = __shfl_xor_sync(~0u, v.x, 16);
            float oy = __shfl_xor_sync(~0u, v.y, 16);
            float oz = __shfl_xor_sync(~0u, v.z, 16);
            float ow = __shfl_xor_sync(~0u, v.w, 16);
            if (lane < 16) {                          // even row pairs with r+1
                int p = r >> 1;
                *(uint4*)&Bs[p * BPN + c4] = make_uint4(
                    pack2h(v.x, ox), pack2h(v.y, oy), pack2h(v.z, oz), pack2h(v.w, ow));
            }
        }
        __syncthreads();

        #pragma unroll
        for (int ks = 0; ks < 2; ks++) {
            unsigned ah[2][4], al[2][4];
            #pragma unroll
            for (int mt = 0; mt < 2; mt++) {
                int rb = wm * 32 + mt * 16;
                uint2 t;
                t = As[(rb + g    ) * APG + ks*8 + c    ]; ah[mt][0]=t.x; al[mt][0]=t.y;
                t = As[(rb + g + 8) * APG + ks*8 + c    ]; ah[mt][1]=t.x; al[mt][1]=t.y;
                t = As[(rb + g    ) * APG + ks*8 + c + 4]; ah[mt][2]=t.x; al[mt][2]=t.y;
                t = As[(rb + g + 8) * APG + ks*8 + c + 4]; ah[mt][3]=t.x; al[mt][3]=t.y;
            }
            #pragma unroll
            for (int nt = 0; nt < 4; nt++) {
                int n = wn * 32 + nt * 8 + g;
                unsigned bb[2] = { Bs[(ks*8 + c    ) * BPN + n],
                                   Bs[(ks*8 + c + 4) * BPN + n] };
                mma2h(acc[0][nt], ah[0], al[0], bb);
                mma2h(acc[1][nt], ah[1], al[1], bb);
            }
        }
        __syncthreads();
    }
    #pragma unroll
    for (int mt = 0; mt < 2; mt++)
        #pragma unroll
        for (int nt = 0; nt < 4; nt++) {
            int r  = row0 + wm * 32 + mt * 16 + g;
            int cc = col0 + wn * 32 + nt * 8 + 2 * c;
            float b0 = bias ? bias[cc] : 0.f, b1 = bias ? bias[cc + 1] : 0.f;
            *(float2*)&Cout[(size_t)r * Nc + cc] =
                make_float2(acc[mt][nt][0] + b0, acc[mt][nt][1] + b1);
            *(float2*)&Cout[(size_t)(r + 8) * Nc + cc] =
                make_float2(acc[mt][nt][2] + b0, acc[mt][nt][3] + b1);
        }
}

// ---------------------------------------------------------------------------
// Flash attention. Block = (bh, 128 Q rows), 256 thr = 8 warps, warp = 16 rows.
// S = Q*K^T in 3xBF16 (exp-sensitive); O += P*V in 2xFP16 (P split, V rounded).
// Q fragments in registers; K bf16-split pairs; V fp16 pairs along j.
// ---------------------------------------------------------------------------
#define KP  36   // Ks pitch (uint2),    ==4 mod 16
#define VPN 72   // Vs pitch (unsigned), ==8 mod 32
#define QSP 68   // Q staging pitch (floats)
#define ATTN_SMEM_B (128*QSP*4)   // 34816 >= (64*KP*8 + 32*VPN*4) = 27648

__global__ void attn_h(const float* __restrict__ qkv, float* __restrict__ O)
{
    __shared__ char smraw[ATTN_SMEM_B];
    float*    qstage = (float*)smraw;         // [128][QSP] (prologue only)
    uint2*    Ks = (uint2*)smraw;             // [64][KP]  bf16 {hi(d-pair), lo}
    unsigned* Vs = (unsigned*)(Ks + 64 * KP); // [32][VPN] fp16 hi (j-pair) per d

    const int tid = threadIdx.x, lane = tid & 31, warp = tid >> 5;
    const int g = lane >> 2, c = lane & 3;
    const int rb = warp * 16;
    const int bh = blockIdx.y, b = bh >> 3, h = bh & 7;
    const int q0 = blockIdx.x * 128;
    const float* qb = qkv + (size_t)b * N_ * F3 + h * 64;
    const float* kb = qb + C_;
    const float* vb = qb + 2 * C_;

    // ---- prologue: stage Q (scaled), split bf16 fragments into registers
    #pragma unroll
    for (int i = 0; i < 8; i++) {
        int idx = tid + i * 256;
        int r = idx >> 4, c4 = (idx & 15) * 4;
        float4 v = *(const float4*)&qb[(size_t)(q0 + r) * F3 + c4];
        v.x *= SCALE; v.y *= SCALE; v.z *= SCALE; v.w *= SCALE;
        *(float4*)&qstage[r * QSP + c4] = v;
    }
    __syncthreads();
    unsigned qh[4][4], ql[4][4];
    #pragma unroll
    for (int ks = 0; ks < 4; ks++) {
        float2 t0 = *(const float2*)&qstage[(rb + g    ) * QSP + ks*16 + 2*c    ];
        float2 t1 = *(const float2*)&qstage[(rb + g + 8) * QSP + ks*16 + 2*c    ];
        float2 t2 = *(const float2*)&qstage[(rb + g    ) * QSP + ks*16 + 2*c + 8];
        float2 t3 = *(const float2*)&qstage[(rb + g + 8) * QSP + ks*16 + 2*c + 8];
        split2b(t0.x, t0.y, qh[ks][0], ql[ks][0]);
        split2b(t1.x, t1.y, qh[ks][1], ql[ks][1]);
        split2b(t2.x, t2.y, qh[ks][2], ql[ks][2]);
        split2b(t3.x, t3.y, qh[ks][3], ql[ks][3]);
    }

    float m0 = -INFINITY, m1 = -INFINITY, l0 = 0.f, l1 = 0.f;
    float acc[8][4] = {};

    for (int j0 = 0; j0 < N_; j0 += 64) {
        __syncthreads();   // protects Ks/Vs reuse (and qstage on first iter)
        #pragma unroll
        for (int i = 0; i < 4; i++) {
            int idx = tid + i * 256;
            int r = idx >> 4, c4 = (idx & 15) * 4;
            // K: bf16 split, pairs along d
            float4 kv = *(const float4*)&kb[(size_t)(j0 + r) * F3 + c4];
            unsigned h0,l0h,h1,l1h;
            split2b(kv.x, kv.y, h0, l0h);
            split2b(kv.z, kv.w, h1, l1h);
            *(uint4*)&Ks[r * KP + (c4 >> 1)] = make_uint4(h0, l0h, h1, l1h);
            // V: fp16 rounded, pairs along j (row r pairs with r^1 via lane^16)
            float4 vv = *(const float4*)&vb[(size_t)(j0 + r) * F3 + c4];
            float ox = __shfl_xor_sync(~0u, vv.x, 16);
            float oy = __shfl_xor_sync(~0u, vv.y, 16);
            float oz = __shfl_xor_sync(~0u, vv.z, 16);
            float ow = __shfl_xor_sync(~0u, vv.w, 16);
            if (lane < 16) {
                int p = r >> 1;
                *(uint4*)&Vs[p * VPN + c4] = make_uint4(
                    pack2h(vv.x, ox), pack2h(vv.y, oy), pack2h(vv.z, oz), pack2h(vv.w, ow));
            }
        }
        __syncthreads();

        // ---- S = Q @ K^T (3xBF16, k-dim = d)
        float sf[8][4] = {};
        #pragma unroll
        for (int ks = 0; ks < 4; ks++) {
            #pragma unroll
            for (int nt = 0; nt < 8; nt++) {
                uint2 t0 = Ks[(nt*8 + g) * KP + ks*8 + c    ];
                uint2 t1 = Ks[(nt*8 + g) * KP + ks*8 + c + 4];
                unsigned bh2[2] = {t0.x, t1.x}, bl2[2] = {t0.y, t1.y};
                mma3b(sf[nt], qh[ks], ql[ks], bh2, bl2);
            }
        }

        // ---- online softmax (rows g / g+8, quad-reduced)
        float mx0 = -INFINITY, mx1 = -INFINITY;
        #pragma unroll
        for (int nt = 0; nt < 8; nt++) {
            mx0 = fmaxf(mx0, fmaxf(sf[nt][0], sf[nt][1]));
            mx1 = fmaxf(mx1, fmaxf(sf[nt][2], sf[nt][3]));
        }
        mx0 = fmaxf(mx0, __shfl_xor_sync(~0u, mx0, 1));
        mx0 = fmaxf(mx0, __shfl_xor_sync(~0u, mx0, 2));
        mx1 = fmaxf(mx1, __shfl_xor_sync(~0u, mx1, 1));
        mx1 = fmaxf(mx1, __shfl_xor_sync(~0u, mx1, 2));
        float m0n = fmaxf(m0, mx0), m1n = fmaxf(m1, mx1);
        float al0 = __expf(m0 - m0n), al1 = __expf(m1 - m1n);  // 0 on first tile
        float s0 = 0.f, s1 = 0.f;
        #pragma unroll
        for (int nt = 0; nt < 8; nt++) {
            sf[nt][0] = __expf(sf[nt][0] - m0n);
            sf[nt][1] = __expf(sf[nt][1] - m0n);
            sf[nt][2] = __expf(sf[nt][2] - m1n);
            sf[nt][3] = __expf(sf[nt][3] - m1n);
            s0 += sf[nt][0] + sf[nt][1];
            s1 += sf[nt][2] + sf[nt][3];
        }
        s0 += __shfl_xor_sync(~0u, s0, 1); s0 += __shfl_xor_sync(~0u, s0, 2);
        s1 += __shfl_xor_sync(~0u, s1, 1); s1 += __shfl_xor_sync(~0u, s1, 2);
        l0 = l0 * al0 + s0;  l1 = l1 * al1 + s1;
        m0 = m0n;            m1 = m1n;
        #pragma unroll
        for (int nt = 0; nt < 8; nt++) {
            acc[nt][0] *= al0; acc[nt][1] *= al0;
            acc[nt][2] *= al1; acc[nt][3] *= al1;
        }

        // ---- O += P @ V (2xFP16: P split in-register, V rounded; k-dim = j)
        #pragma unroll
        for (int ks = 0; ks < 4; ks++) {
            unsigned pah[4], pal[4];
            split2h(sf[2*ks  ][0], sf[2*ks  ][1], pah[0], pal[0]);
            split2h(sf[2*ks  ][2], sf[2*ks  ][3], pah[1], pal[1]);
            split2h(sf[2*ks+1][0], sf[2*ks+1][1], pah[2], pal[2]);
            split2h(sf[2*ks+1][2], sf[2*ks+1][3], pah[3], pal[3]);
            #pragma unroll
            for (int nt = 0; nt < 8; nt++) {
                unsigned bb[2] = { Vs[(ks*8 + c    ) * VPN + nt*8 + g],
                                   Vs[(ks*8 + c + 4) * VPN + nt*8 + g] };
                mma2h(acc[nt], pah, pal, bb);
            }
        }
    }

    // ---- epilogue: /l, write O in (b,h,n,d) layout
    float i0 = 1.f / l0, i1 = 1.f / l1;
    float* ob = O + ((size_t)(b * H_ + h) * N_ + q0 + rb) * D_;
    #pragma unroll
    for (int nt = 0; nt < 8; nt++) {
        int cc = nt * 8 + 2 * c;
        *(float2*)&ob[(size_t)g * D_ + cc]       = make_float2(acc[nt][0]*i0, acc[nt][1]*i0);
        *(float2*)&ob[(size_t)(g + 8) * D_ + cc] = make_float2(acc[nt][2]*i1, acc[nt][3]*i1);
    }
}

// ---------------------------------------------------------------------------
extern "C" void kernel_launch(void* const* d_in, const int* in_sizes, int n_in,
                              void* d_out, int out_size)
{
    const float* x      = (const float*)d_in[0];
    const float* qkv_w  = (const float*)d_in[1];
    const float* proj_w = (const float*)d_in[2];
    const float* proj_b = (const float*)d_in[3];
    float* out = (float*)d_out;

    float *qkv_p, *o_p;
    cudaGetSymbolAddress((void**)&qkv_p, g_qkv);
    cudaGetSymbolAddress((void**)&o_p,   g_o);

    // 1) QKV projection: (4096x512) @ (512x1536)
    dim3 g1(F3 / 64, (B_ * N_) / 128);
    gemm_h2<<<g1, 256>>>(x, qkv_w, nullptr, qkv_p, B_ * N_, F3, C_);

    // 2) Flash attention per (bh, 128-row q-tile)
    dim3 g2(N_ / 128, B_ * H_);
    attn_h<<<g2, 256>>>(qkv_p, o_p);

    // 3) Output projection (reads O as (4096,512) == reshape-without-transpose)
    dim3 g3(C_ / 64, (B_ * N_) / 128);
    gemm_h2<<<g3, 256>>>(o_p, proj_w, proj_b, out, B_ * N_, C_, C_);
}

// round 8
// speedup vs baseline: 6.7580x; 1.2117x over previous
#include <cuda_runtime.h>
#include <cuda_bf16.h>
#include <cuda_fp16.h>
#include <math.h>

#define B_ 2
#define N_ 2048
#define C_ 512
#define H_ 8
#define D_ 64
#define F3 1536
#define SCALE 0.125f

// ---------------------------------------------------------------------------
// Scratch (device globals: allocation-free per harness rules)
// ---------------------------------------------------------------------------
__device__ float    g_qkv[(size_t)B_*N_*F3];    // fp32 qkv (b*N+n, 1536)
__device__ uint2    g_xs [4096*256];            // x split fp16 {hi,lo} k-pairs
__device__ unsigned g_wq [256*1536];            // qkv_w packed fp16 k-pairs
__device__ unsigned g_wp [256*512];             // proj_w packed fp16 k-pairs
__device__ uint2    g_kp [(size_t)32768*32];    // K split bf16 {hi,lo} d-pairs
__device__ unsigned g_vp [(size_t)16*1024*64];  // V fp16 j-pairs per d
__device__ uint2    g_op [4096*256];            // attn out split fp16 k-pairs

// ---------------------------------------------------------------------------
// split/pack helpers
// ---------------------------------------------------------------------------
__device__ __forceinline__ void split2b(float x, float y, unsigned &hi, unsigned &lo) {
    __nv_bfloat162 h = __floats2bfloat162_rn(x, y);
    float hx = __bfloat162float(h.x), hy = __bfloat162float(h.y);
    __nv_bfloat162 l = __floats2bfloat162_rn(x - hx, y - hy);
    hi = *reinterpret_cast<const unsigned*>(&h);
    lo = *reinterpret_cast<const unsigned*>(&l);
}
__device__ __forceinline__ void split2h(float x, float y, unsigned &hi, unsigned &lo) {
    __half2 h = __floats2half2_rn(x, y);
    float hx = __half2float(h.x), hy = __half2float(h.y);
    __half2 l = __floats2half2_rn(x - hx, y - hy);
    hi = *reinterpret_cast<const unsigned*>(&h);
    lo = *reinterpret_cast<const unsigned*>(&l);
}
__device__ __forceinline__ unsigned pack2h(float x, float y) {
    __half2 h = __floats2half2_rn(x, y);
    return *reinterpret_cast<const unsigned*>(&h);
}
__device__ __forceinline__ void mma16b(float c[4], const unsigned a[4], const unsigned b[2]) {
    asm volatile("mma.sync.aligned.m16n8k16.row.col.f32.bf16.bf16.f32 "
        "{%0,%1,%2,%3}, {%4,%5,%6,%7}, {%8,%9}, {%0,%1,%2,%3};\n"
        : "+f"(c[0]), "+f"(c[1]), "+f"(c[2]), "+f"(c[3])
        : "r"(a[0]), "r"(a[1]), "r"(a[2]), "r"(a[3]), "r"(b[0]), "r"(b[1]));
}
__device__ __forceinline__ void mma3b(float c[4], const unsigned ah[4], const unsigned al[4],
                                      const unsigned bh[2], const unsigned bl[2]) {
    mma16b(c, ah, bh);
    mma16b(c, ah, bl);
    mma16b(c, al, bh);
}
__device__ __forceinline__ void mma16h(float c[4], const unsigned a[4], const unsigned b[2]) {
    asm volatile("mma.sync.aligned.m16n8k16.row.col.f32.f16.f16.f32 "
        "{%0,%1,%2,%3}, {%4,%5,%6,%7}, {%8,%9}, {%0,%1,%2,%3};\n"
        : "+f"(c[0]), "+f"(c[1]), "+f"(c[2]), "+f"(c[3])
        : "r"(a[0]), "r"(a[1]), "r"(a[2]), "r"(a[3]), "r"(b[0]), "r"(b[1]));
}
__device__ __forceinline__ void mma2h(float c[4], const unsigned ah[4], const unsigned al[4],
                                      const unsigned b[2]) {
    mma16h(c, ah, b);
    mma16h(c, al, b);
}

// ---------------------------------------------------------------------------
// prep_static: x -> split fp16 pairs; qkv_w/proj_w -> packed fp16 k-pairs.
// ---------------------------------------------------------------------------
__global__ void prep_static(const float* __restrict__ x,
                            const float* __restrict__ wq,
                            const float* __restrict__ wp)
{
    int u = blockIdx.x * 256 + threadIdx.x;
    if (u < 262144) {                               // x: 4096 rows x 64 units(8 f)
        int r = u >> 6, f0 = (u & 63) * 8;
        float4 v0 = *(const float4*)&x[(size_t)r * 512 + f0];
        float4 v1 = *(const float4*)&x[(size_t)r * 512 + f0 + 4];
        unsigned h0,l0,h1,l1,h2,l2,h3,l3;
        split2h(v0.x, v0.y, h0, l0);  split2h(v0.z, v0.w, h1, l1);
        split2h(v1.x, v1.y, h2, l2);  split2h(v1.z, v1.w, h3, l3);
        uint2* dst = &g_xs[(size_t)r * 256 + (f0 >> 1)];
        *(uint4*)dst       = make_uint4(h0, l0, h1, l1);
        *(uint4*)(dst + 2) = make_uint4(h2, l2, h3, l3);
    } else if (u < 262144 + 98304) {                // qkv_w: 256 kp x 384 units(4 c)
        int t = u - 262144;
        int kp = t / 384, c4 = (t % 384) * 4;
        float4 a = *(const float4*)&wq[(size_t)(2*kp    ) * F3 + c4];
        float4 b = *(const float4*)&wq[(size_t)(2*kp + 1) * F3 + c4];
        *(uint4*)&g_wq[(size_t)kp * F3 + c4] = make_uint4(
            pack2h(a.x, b.x), pack2h(a.y, b.y), pack2h(a.z, b.z), pack2h(a.w, b.w));
    } else if (u < 262144 + 98304 + 32768) {        // proj_w: 256 kp x 128 units
        int t = u - 262144 - 98304;
        int kp = t / 128, c4 = (t % 128) * 4;
        float4 a = *(const float4*)&wp[(size_t)(2*kp    ) * 512 + c4];
        float4 b = *(const float4*)&wp[(size_t)(2*kp + 1) * 512 + c4];
        *(uint4*)&g_wp[(size_t)kp * 512 + c4] = make_uint4(
            pack2h(a.x, b.x), pack2h(a.y, b.y), pack2h(a.z, b.z), pack2h(a.w, b.w));
    }
}

// ---------------------------------------------------------------------------
// prep_kv: K -> bf16 split d-pairs [bh*2048+n][32]; V -> fp16 j-pairs [bh][jp][64]
// ---------------------------------------------------------------------------
__global__ void prep_kv()
{
    int u = blockIdx.x * 256 + threadIdx.x;
    if (u < 262144) {                               // K: 32768 rows x 8 units(8 f)
        int krow = u >> 3, f0 = (u & 7) * 8;
        int b = krow >> 14, h = (krow >> 11) & 7, n = krow & 2047;
        const float* src = &g_qkv[((size_t)(b*N_ + n)) * F3 + C_ + h*64 + f0];
        float4 v0 = *(const float4*)src;
        float4 v1 = *(const float4*)(src + 4);
        unsigned h0,l0,h1,l1,h2,l2,h3,l3;
        split2b(v0.x, v0.y, h0, l0);  split2b(v0.z, v0.w, h1, l1);
        split2b(v1.x, v1.y, h2, l2);  split2b(v1.z, v1.w, h3, l3);
        uint2* dst = &g_kp[(size_t)krow * 32 + (f0 >> 1)];
        *(uint4*)dst       = make_uint4(h0, l0, h1, l1);
        *(uint4*)(dst + 2) = make_uint4(h2, l2, h3, l3);
    } else if (u < 524288) {                        // V: 16 bh x 1024 jp x 16 units(4 d)
        int t = u - 262144;
        int bh = t >> 14, rem = t & 16383, jp = rem >> 4, d4 = (rem & 15) * 4;
        int b = bh >> 3, h = bh & 7;
        const float* s0 = &g_qkv[((size_t)(b*N_ + 2*jp)) * F3 + 2*C_ + h*64 + d4];
        float4 a = *(const float4*)s0;
        float4 cc = *(const float4*)(s0 + F3);
        *(uint4*)&g_vp[(size_t)bh * 65536 + jp * 64 + d4] = make_uint4(
            pack2h(a.x, cc.x), pack2h(a.y, cc.y), pack2h(a.z, cc.z), pack2h(a.w, cc.w));
    }
}

// ---------------------------------------------------------------------------
// GEMM from pre-split operands: C = A(MxK) @ B(KxNc) [+bias], 2xFP16 mma.
// Block 128x64, BK=32, 256 thr, warp tile 32x32. Register-prefetch pipeline.
// ---------------------------------------------------------------------------
#define APG 20   // As pitch (uint2), ==4 mod 16
#define BPN 72   // Bs pitch (unsigned), ==8 mod 32
__global__ void gemm_fast(const uint2* __restrict__ A, const unsigned* __restrict__ Bp,
                          const float* __restrict__ bias, float* __restrict__ Cout,
                          int M, int Nc, int K)
{
    __shared__ uint2    As[128 * APG];
    __shared__ unsigned Bs[16 * BPN];
    const int tid = threadIdx.x, lane = tid & 31, warp = tid >> 5;
    const int wm = warp >> 1, wn = warp & 1;
    const int row0 = blockIdx.y * 128, col0 = blockIdx.x * 64;
    const int g = lane >> 2, c = lane & 3;
    const int Kp2 = K >> 1;

    float acc[2][4][4] = {};
    uint4 pa[4], pb;

    // prefetch tile 0
    #pragma unroll
    for (int i = 0; i < 4; i++) {
        int idx = tid + i * 256, r = idx >> 3, c2 = (idx & 7) * 2;
        pa[i] = *(const uint4*)&A[(size_t)(row0 + r) * Kp2 + c2];
    }
    { int r = tid >> 4, c4 = (tid & 15) * 4;
      pb = *(const uint4*)&Bp[(size_t)r * Nc + col0 + c4]; }

    for (int k0 = 0; k0 < K; k0 += 32) {
        // store prefetched tile
        #pragma unroll
        for (int i = 0; i < 4; i++) {
            int idx = tid + i * 256, r = idx >> 3, c2 = (idx & 7) * 2;
            *(uint4*)&As[r * APG + c2] = pa[i];
        }
        { int r = tid >> 4, c4 = (tid & 15) * 4;
          *(uint4*)&Bs[r * BPN + c4] = pb; }
        __syncthreads();

        if (k0 + 32 < K) {                       // prefetch next tile
            int kp0 = (k0 + 32) >> 1;
            #pragma unroll
            for (int i = 0; i < 4; i++) {
                int idx = tid + i * 256, r = idx >> 3, c2 = (idx & 7) * 2;
                pa[i] = *(const uint4*)&A[(size_t)(row0 + r) * Kp2 + kp0 + c2];
            }
            int r = tid >> 4, c4 = (tid & 15) * 4;
            pb = *(const uint4*)&Bp[(size_t)(kp0 + r) * Nc + col0 + c4];
        }

        #pragma unroll
        for (int ks = 0; ks < 2; ks++) {
            unsigned ah[2][4], al[2][4];
            #pragma unroll
            for (int mt = 0; mt < 2; mt++) {
                int rbl = wm * 32 + mt * 16;
                uint2 t;
                t = As[(rbl + g    ) * APG + ks*8 + c    ]; ah[mt][0]=t.x; al[mt][0]=t.y;
                t = As[(rbl + g + 8) * APG + ks*8 + c    ]; ah[mt][1]=t.x; al[mt][1]=t.y;
                t = As[(rbl + g    ) * APG + ks*8 + c + 4]; ah[mt][2]=t.x; al[mt][2]=t.y;
                t = As[(rbl + g + 8) * APG + ks*8 + c + 4]; ah[mt][3]=t.x; al[mt][3]=t.y;
            }
            #pragma unroll
            for (int nt = 0; nt < 4; nt++) {
                int n = wn * 32 + nt * 8 + g;
                unsigned bb[2] = { Bs[(ks*8 + c    ) * BPN + n],
                                   Bs[(ks*8 + c + 4) * BPN + n] };
                mma2h(acc[0][nt], ah[0], al[0], bb);
                mma2h(acc[1][nt], ah[1], al[1], bb);
            }
        }
        __syncthreads();
    }
    #pragma unroll
    for (int mt = 0; mt < 2; mt++)
        #pragma unroll
        for (int nt = 0; nt < 4; nt++) {
            int r  = row0 + wm * 32 + mt * 16 + g;
            int cc = col0 + wn * 32 + nt * 8 + 2 * c;
            float b0 = bias ? bias[cc] : 0.f, b1 = bias ? bias[cc + 1] : 0.f;
            *(float2*)&Cout[(size_t)r * Nc + cc] =
                make_float2(acc[mt][nt][0] + b0, acc[mt][nt][1] + b1);
            *(float2*)&Cout[(size_t)(r + 8) * Nc + cc] =
                make_float2(acc[mt][nt][2] + b0, acc[mt][nt][3] + b1);
        }
}

// ---------------------------------------------------------------------------
// Flash attention from pre-converted K/V. Block = (bh, 128 Q rows), 256 thr.
// Mainloop = pure smem copies + mma + softmax (no cvt/shfl on K/V).
// Epilogue writes pre-split fp16 pairs = proj GEMM A operand.
// ---------------------------------------------------------------------------
#define KP  36   // Ks pitch (uint2),    ==4 mod 16
#define VPN 72   // Vs pitch (unsigned), ==8 mod 32
#define QSP 68   // Q staging pitch (floats)
#define ATTN_SMEM_B (128*QSP*4)   // 34816 >= 64*KP*8 + 32*VPN*4 = 27648

__global__ void attn_f(const float* __restrict__ qkv, uint2* __restrict__ Op)
{
    __shared__ char smraw[ATTN_SMEM_B];
    float*    qstage = (float*)smraw;           // prologue only
    uint2*    Ks = (uint2*)smraw;               // [64][KP]  bf16 {hi,lo} d-pairs
    unsigned* Vs = (unsigned*)(Ks + 64 * KP);   // [32][VPN] fp16 j-pairs per d

    const int tid = threadIdx.x, lane = tid & 31, warp = tid >> 5;
    const int g = lane >> 2, c = lane & 3;
    const int rb = warp * 16;
    const int bh = blockIdx.y, b = bh >> 3, h = bh & 7;
    const int q0 = blockIdx.x * 128;
    const float* qb = qkv + (size_t)b * N_ * F3 + h * 64;
    const uint2* kpb = g_kp + (size_t)bh * N_ * 32;
    const unsigned* vpb = g_vp + (size_t)bh * 65536;

    // ---- prologue: stage Q (scaled), split bf16 fragments into registers
    #pragma unroll
    for (int i = 0; i < 8; i++) {
        int idx = tid + i * 256;
        int r = idx >> 4, c4 = (idx & 15) * 4;
        float4 v = *(const float4*)&qb[(size_t)(q0 + r) * F3 + c4];
        v.x *= SCALE; v.y *= SCALE; v.z *= SCALE; v.w *= SCALE;
        *(float4*)&qstage[r * QSP + c4] = v;
    }
    __syncthreads();
    unsigned qh[4][4], ql[4][4];
    #pragma unroll
    for (int ks = 0; ks < 4; ks++) {
        float2 t0 = *(const float2*)&qstage[(rb + g    ) * QSP + ks*16 + 2*c    ];
        float2 t1 = *(const float2*)&qstage[(rb + g + 8) * QSP + ks*16 + 2*c    ];
        float2 t2 = *(const float2*)&qstage[(rb + g    ) * QSP + ks*16 + 2*c + 8];
        float2 t3 = *(const float2*)&qstage[(rb + g + 8) * QSP + ks*16 + 2*c + 8];
        split2b(t0.x, t0.y, qh[ks][0], ql[ks][0]);
        split2b(t1.x, t1.y, qh[ks][1], ql[ks][1]);
        split2b(t2.x, t2.y, qh[ks][2], ql[ks][2]);
        split2b(t3.x, t3.y, qh[ks][3], ql[ks][3]);
    }

    // ---- prefetch tile 0 into registers
    uint4 kr[4], vr[2];
    #pragma unroll
    for (int i = 0; i < 4; i++) {
        int idx = tid + i * 256, r = idx >> 4, c2 = (idx & 15) * 2;
        kr[i] = *(const uint4*)&kpb[(size_t)r * 32 + c2];
    }
    #pragma unroll
    for (int i = 0; i < 2; i++) {
        int idx = tid + i * 256, r = idx >> 4, c4 = (idx & 15) * 4;
        vr[i] = *(const uint4*)&vpb[(size_t)r * 64 + c4];
    }
    __syncthreads();           // qstage reads complete before overwrite

    // store tile 0
    #pragma unroll
    for (int i = 0; i < 4; i++) {
        int idx = tid + i * 256, r = idx >> 4, c2 = (idx & 15) * 2;
        *(uint4*)&Ks[r * KP + c2] = kr[i];
    }
    #pragma unroll
    for (int i = 0; i < 2; i++) {
        int idx = tid + i * 256, r = idx >> 4, c4 = (idx & 15) * 4;
        *(uint4*)&Vs[r * VPN + c4] = vr[i];
    }

    float m0 = -INFINITY, m1 = -INFINITY, l0 = 0.f, l1 = 0.f;
    float acc[8][4] = {};

    for (int j0 = 0; j0 < N_; j0 += 64) {
        __syncthreads();       // tile in smem ready
        const bool nxt = (j0 + 64 < N_);
        if (nxt) {             // prefetch next tile
            #pragma unroll
            for (int i = 0; i < 4; i++) {
                int idx = tid + i * 256, r = idx >> 4, c2 = (idx & 15) * 2;
                kr[i] = *(const uint4*)&kpb[(size_t)(j0 + 64 + r) * 32 + c2];
            }
            #pragma unroll
            for (int i = 0; i < 2; i++) {
                int idx = tid + i * 256, r = idx >> 4, c4 = (idx & 15) * 4;
                vr[i] = *(const uint4*)&vpb[(size_t)((j0 >> 1) + 32 + r) * 64 + c4];
            }
        }

        // ---- S = Q @ K^T (3xBF16)
        float sf[8][4] = {};
        #pragma unroll
        for (int ks = 0; ks < 4; ks++) {
            #pragma unroll
            for (int nt = 0; nt < 8; nt++) {
                uint2 t0 = Ks[(nt*8 + g) * KP + ks*8 + c    ];
                uint2 t1 = Ks[(nt*8 + g) * KP + ks*8 + c + 4];
                unsigned bh2[2] = {t0.x, t1.x}, bl2[2] = {t0.y, t1.y};
                mma3b(sf[nt], qh[ks], ql[ks], bh2, bl2);
            }
        }

        // ---- online softmax
        float mx0 = -INFINITY, mx1 = -INFINITY;
        #pragma unroll
        for (int nt = 0; nt < 8; nt++) {
            mx0 = fmaxf(mx0, fmaxf(sf[nt][0], sf[nt][1]));
            mx1 = fmaxf(mx1, fmaxf(sf[nt][2], sf[nt][3]));
        }
        mx0 = fmaxf(mx0, __shfl_xor_sync(~0u, mx0, 1));
        mx0 = fmaxf(mx0, __shfl_xor_sync(~0u, mx0, 2));
        mx1 = fmaxf(mx1, __shfl_xor_sync(~0u, mx1, 1));
        mx1 = fmaxf(mx1, __shfl_xor_sync(~0u, mx1, 2));
        float m0n = fmaxf(m0, mx0), m1n = fmaxf(m1, mx1);
        float al0 = __expf(m0 - m0n), al1 = __expf(m1 - m1n);
        float s0 = 0.f, s1 = 0.f;
        #pragma unroll
        for (int nt = 0; nt < 8; nt++) {
            sf[nt][0] = __expf(sf[nt][0] - m0n);
            sf[nt][1] = __expf(sf[nt][1] - m0n);
            sf[nt][2] = __expf(sf[nt][2] - m1n);
            sf[nt][3] = __expf(sf[nt][3] - m1n);
            s0 += sf[nt][0] + sf[nt][1];
            s1 += sf[nt][2] + sf[nt][3];
        }
        s0 += __shfl_xor_sync(~0u, s0, 1); s0 += __shfl_xor_sync(~0u, s0, 2);
        s1 += __shfl_xor_sync(~0u, s1, 1); s1 += __shfl_xor_sync(~0u, s1, 2);
        l0 = l0 * al0 + s0;  l1 = l1 * al1 + s1;
        m0 = m0n;            m1 = m1n;
        #pragma unroll
        for (int nt = 0; nt < 8; nt++) {
            acc[nt][0] *= al0; acc[nt][1] *= al0;
            acc[nt][2] *= al1; acc[nt][3] *= al1;
        }

        // ---- O += P @ V (2xFP16, P split in-register)
        #pragma unroll
        for (int ks = 0; ks < 4; ks++) {
            unsigned pah[4], pal[4];
            split2h(sf[2*ks  ][0], sf[2*ks  ][1], pah[0], pal[0]);
            split2h(sf[2*ks  ][2], sf[2*ks  ][3], pah[1], pal[1]);
            split2h(sf[2*ks+1][0], sf[2*ks+1][1], pah[2], pal[2]);
            split2h(sf[2*ks+1][2], sf[2*ks+1][3], pah[3], pal[3]);
            #pragma unroll
            for (int nt = 0; nt < 8; nt++) {
                unsigned bb[2] = { Vs[(ks*8 + c    ) * VPN + nt*8 + g],
                                   Vs[(ks*8 + c + 4) * VPN + nt*8 + g] };
                mma2h(acc[nt], pah, pal, bb);
            }
        }

        __syncthreads();       // all reads of this tile done
        if (nxt) {             // store next tile
            #pragma unroll
            for (int i = 0; i < 4; i++) {
                int idx = tid + i * 256, r = idx >> 4, c2 = (idx & 15) * 2;
                *(uint4*)&Ks[r * KP + c2] = kr[i];
            }
            #pragma unroll
            for (int i = 0; i < 2; i++) {
                int idx = tid + i * 256, r = idx >> 4, c4 = (idx & 15) * 4;
                *(uint4*)&Vs[r * VPN + c4] = vr[i];
            }
        }
    }

    // ---- epilogue: /l, write pre-split fp16 pairs (= proj A operand)
    float i0 = 1.f / l0, i1 = 1.f / l1;
    size_t f0 = ((size_t)bh * N_ + q0 + rb + g    ) * 64;
    size_t f1 = ((size_t)bh * N_ + q0 + rb + g + 8) * 64;
    #pragma unroll
    for (int nt = 0; nt < 8; nt++) {
        int cc = nt * 8 + 2 * c;
        unsigned hh, ll;
        split2h(acc[nt][0] * i0, acc[nt][1] * i0, hh, ll);
        Op[(f0 + cc) >> 1] = make_uint2(hh, ll);
        split2h(acc[nt][2] * i1, acc[nt][3] * i1, hh, ll);
        Op[(f1 + cc) >> 1] = make_uint2(hh, ll);
    }
}

// ---------------------------------------------------------------------------
extern "C" void kernel_launch(void* const* d_in, const int* in_sizes, int n_in,
                              void* d_out, int out_size)
{
    const float* x      = (const float*)d_in[0];
    const float* qkv_w  = (const float*)d_in[1];
    const float* proj_w = (const float*)d_in[2];
    const float* proj_b = (const float*)d_in[3];
    float* out = (float*)d_out;

    float *qkv_p;  uint2 *xs_p, *op_p;  unsigned *wq_p, *wp_p;
    cudaGetSymbolAddress((void**)&qkv_p, g_qkv);
    cudaGetSymbolAddress((void**)&xs_p,  g_xs);
    cudaGetSymbolAddress((void**)&wq_p,  g_wq);
    cudaGetSymbolAddress((void**)&wp_p,  g_wp);
    cudaGetSymbolAddress((void**)&op_p,  g_op);

    // 0) pre-split x + pack weights
    prep_static<<<1536, 256>>>(x, qkv_w, proj_w);

    // 1) QKV projection: (4096x512) @ (512x1536), pre-split operands
    dim3 g1(F3 / 64, 4096 / 128);
    gemm_fast<<<g1, 256>>>(xs_p, wq_p, nullptr, qkv_p, 4096, F3, C_);

    // 2) pre-convert K (bf16 split) and V (fp16 pairs)
    prep_kv<<<2048, 256>>>();

    // 3) flash attention -> pre-split O
    dim3 g2(N_ / 128, B_ * H_);
    attn_f<<<g2, 256>>>(qkv_p, op_p);

    // 4) output projection: (4096x512) @ (512x512) + bias
    dim3 g3(C_ / 64, 4096 / 128);
    gemm_fast<<<g3, 256>>>(op_p, wp_p, proj_b, out, 4096, C_, C_);
}

// round 9
// speedup vs baseline: 7.1677x; 1.0606x over previous
#include <cuda_runtime.h>
#include <cuda_bf16.h>
#include <cuda_fp16.h>
#include <math.h>

#define B_ 2
#define N_ 2048
#define C_ 512
#define H_ 8
#define D_ 64
#define F3 1536
#define SCALE 0.125f

// ---------------------------------------------------------------------------
// Scratch (device globals: allocation-free per harness rules)
// ---------------------------------------------------------------------------
__device__ float    g_qkv[(size_t)B_*N_*F3];    // fp32 qkv (b*N+n, 1536)
__device__ uint2    g_xs [4096*256];            // x split fp16 {hi,lo} k-pairs
__device__ unsigned g_wq [256*1536];            // qkv_w packed fp16 k-pairs
__device__ unsigned g_wp [256*512];             // proj_w packed fp16 k-pairs
__device__ uint2    g_kp [(size_t)32768*32];    // K split bf16 {hi,lo} d-pairs
__device__ unsigned g_vp [(size_t)16*1024*64];  // V fp16 j-pairs per d
__device__ uint2    g_op [4096*256];            // attn out split fp16 k-pairs

// ---------------------------------------------------------------------------
// helpers
// ---------------------------------------------------------------------------
__device__ __forceinline__ void split2b(float x, float y, unsigned &hi, unsigned &lo) {
    __nv_bfloat162 h = __floats2bfloat162_rn(x, y);
    float hx = __bfloat162float(h.x), hy = __bfloat162float(h.y);
    __nv_bfloat162 l = __floats2bfloat162_rn(x - hx, y - hy);
    hi = *reinterpret_cast<const unsigned*>(&h);
    lo = *reinterpret_cast<const unsigned*>(&l);
}
__device__ __forceinline__ void split2h(float x, float y, unsigned &hi, unsigned &lo) {
    __half2 h = __floats2half2_rn(x, y);
    float hx = __half2float(h.x), hy = __half2float(h.y);
    __half2 l = __floats2half2_rn(x - hx, y - hy);
    hi = *reinterpret_cast<const unsigned*>(&h);
    lo = *reinterpret_cast<const unsigned*>(&l);
}
__device__ __forceinline__ unsigned pack2h(float x, float y) {
    __half2 h = __floats2half2_rn(x, y);
    return *reinterpret_cast<const unsigned*>(&h);
}
__device__ __forceinline__ void mma16b(float c[4], const unsigned a[4], const unsigned b[2]) {
    asm volatile("mma.sync.aligned.m16n8k16.row.col.f32.bf16.bf16.f32 "
        "{%0,%1,%2,%3}, {%4,%5,%6,%7}, {%8,%9}, {%0,%1,%2,%3};\n"
        : "+f"(c[0]), "+f"(c[1]), "+f"(c[2]), "+f"(c[3])
        : "r"(a[0]), "r"(a[1]), "r"(a[2]), "r"(a[3]), "r"(b[0]), "r"(b[1]));
}
__device__ __forceinline__ void mma3b(float c[4], const unsigned ah[4], const unsigned al[4],
                                      const unsigned bh[2], const unsigned bl[2]) {
    mma16b(c, ah, bh);
    mma16b(c, ah, bl);
    mma16b(c, al, bh);
}
__device__ __forceinline__ void mma16h(float c[4], const unsigned a[4], const unsigned b[2]) {
    asm volatile("mma.sync.aligned.m16n8k16.row.col.f32.f16.f16.f32 "
        "{%0,%1,%2,%3}, {%4,%5,%6,%7}, {%8,%9}, {%0,%1,%2,%3};\n"
        : "+f"(c[0]), "+f"(c[1]), "+f"(c[2]), "+f"(c[3])
        : "r"(a[0]), "r"(a[1]), "r"(a[2]), "r"(a[3]), "r"(b[0]), "r"(b[1]));
}
__device__ __forceinline__ void mma2h(float c[4], const unsigned ah[4], const unsigned al[4],
                                      const unsigned b[2]) {
    mma16h(c, ah, b);
    mma16h(c, al, b);
}
// cp.async (LDGSTS) helpers
__device__ __forceinline__ void cp16(void* smem, const void* gmem) {
    unsigned sa = (unsigned)__cvta_generic_to_shared(smem);
    asm volatile("cp.async.cg.shared.global [%0], [%1], 16;\n" :: "r"(sa), "l"(gmem));
}
#define CP_COMMIT() asm volatile("cp.async.commit_group;\n")
template<int Np> __device__ __forceinline__ void cp_wait() {
    asm volatile("cp.async.wait_group %0;\n" :: "n"(Np));
}

// ---------------------------------------------------------------------------
// prep_static: x -> split fp16 pairs; qkv_w/proj_w -> packed fp16 k-pairs.
// ---------------------------------------------------------------------------
__global__ void prep_static(const float* __restrict__ x,
                            const float* __restrict__ wq,
                            const float* __restrict__ wp)
{
    int u = blockIdx.x * 256 + threadIdx.x;
    if (u < 262144) {                               // x: 4096 rows x 64 units(8 f)
        int r = u >> 6, f0 = (u & 63) * 8;
        float4 v0 = *(const float4*)&x[(size_t)r * 512 + f0];
        float4 v1 = *(const float4*)&x[(size_t)r * 512 + f0 + 4];
        unsigned h0,l0,h1,l1,h2,l2,h3,l3;
        split2h(v0.x, v0.y, h0, l0);  split2h(v0.z, v0.w, h1, l1);
        split2h(v1.x, v1.y, h2, l2);  split2h(v1.z, v1.w, h3, l3);
        uint2* dst = &g_xs[(size_t)r * 256 + (f0 >> 1)];
        *(uint4*)dst       = make_uint4(h0, l0, h1, l1);
        *(uint4*)(dst + 2) = make_uint4(h2, l2, h3, l3);
    } else if (u < 262144 + 98304) {                // qkv_w: 256 kp x 384 units(4 c)
        int t = u - 262144;
        int kp = t / 384, c4 = (t % 384) * 4;
        float4 a = *(const float4*)&wq[(size_t)(2*kp    ) * F3 + c4];
        float4 b = *(const float4*)&wq[(size_t)(2*kp + 1) * F3 + c4];
        *(uint4*)&g_wq[(size_t)kp * F3 + c4] = make_uint4(
            pack2h(a.x, b.x), pack2h(a.y, b.y), pack2h(a.z, b.z), pack2h(a.w, b.w));
    } else if (u < 262144 + 98304 + 32768) {        // proj_w: 256 kp x 128 units
        int t = u - 262144 - 98304;
        int kp = t / 128, c4 = (t % 128) * 4;
        float4 a = *(const float4*)&wp[(size_t)(2*kp    ) * 512 + c4];
        float4 b = *(const float4*)&wp[(size_t)(2*kp + 1) * 512 + c4];
        *(uint4*)&g_wp[(size_t)kp * 512 + c4] = make_uint4(
            pack2h(a.x, b.x), pack2h(a.y, b.y), pack2h(a.z, b.z), pack2h(a.w, b.w));
    }
}

// ---------------------------------------------------------------------------
// prep_kv: K -> bf16 split d-pairs [bh*2048+n][32]; V -> fp16 j-pairs [bh][jp][64]
// ---------------------------------------------------------------------------
__global__ void prep_kv()
{
    int u = blockIdx.x * 256 + threadIdx.x;
    if (u < 262144) {                               // K: 32768 rows x 8 units(8 f)
        int krow = u >> 3, f0 = (u & 7) * 8;
        int b = krow >> 14, h = (krow >> 11) & 7, n = krow & 2047;
        const float* src = &g_qkv[((size_t)(b*N_ + n)) * F3 + C_ + h*64 + f0];
        float4 v0 = *(const float4*)src;
        float4 v1 = *(const float4*)(src + 4);
        unsigned h0,l0,h1,l1,h2,l2,h3,l3;
        split2b(v0.x, v0.y, h0, l0);  split2b(v0.z, v0.w, h1, l1);
        split2b(v1.x, v1.y, h2, l2);  split2b(v1.z, v1.w, h3, l3);
        uint2* dst = &g_kp[(size_t)krow * 32 + (f0 >> 1)];
        *(uint4*)dst       = make_uint4(h0, l0, h1, l1);
        *(uint4*)(dst + 2) = make_uint4(h2, l2, h3, l3);
    } else if (u < 524288) {                        // V: 16 bh x 1024 jp x 16 units(4 d)
        int t = u - 262144;
        int bh = t >> 14, rem = t & 16383, jp = rem >> 4, d4 = (rem & 15) * 4;
        int b = bh >> 3, h = bh & 7;
        const float* s0 = &g_qkv[((size_t)(b*N_ + 2*jp)) * F3 + 2*C_ + h*64 + d4];
        float4 a = *(const float4*)s0;
        float4 cc = *(const float4*)(s0 + F3);
        *(uint4*)&g_vp[(size_t)bh * 65536 + jp * 64 + d4] = make_uint4(
            pack2h(a.x, cc.x), pack2h(a.y, cc.y), pack2h(a.z, cc.z), pack2h(a.w, cc.w));
    }
}

// ---------------------------------------------------------------------------
// GEMM: C = A(MxK) @ B(KxNc) [+bias], pre-split operands, 2xFP16 mma.
// Block 128x64, BK=32, 256 thr. cp.async 2-stage pipeline, 2 CTAs/SM.
// ---------------------------------------------------------------------------
#define APG 20                      // As pitch (uint2), ==4 mod 16
#define BPN 72                      // Bs pitch (unsigned), ==8 mod 32
#define GA_STAGE (128*APG)          // uint2 per stage
#define GB_STAGE (16*BPN)           // unsigned per stage
#define GEMM_SMEM (2*GA_STAGE*8 + 2*GB_STAGE*4)   // 50176 B

__global__ __launch_bounds__(256, 2)
void gemm_cp(const uint2* __restrict__ A, const unsigned* __restrict__ Bp,
             const float* __restrict__ bias, float* __restrict__ Cout,
             int M, int Nc, int K)
{
    extern __shared__ char dsm[];
    uint2*    Asb = (uint2*)dsm;
    unsigned* Bsb = (unsigned*)(dsm + 2*GA_STAGE*8);
    const int tid = threadIdx.x, lane = tid & 31, warp = tid >> 5;
    const int wm = warp >> 1, wn = warp & 1;
    const int row0 = blockIdx.y * 128, col0 = blockIdx.x * 64;
    const int g = lane >> 2, c = lane & 3;
    const int Kp2 = K >> 1, T = K >> 5;

    float acc[2][4][4] = {};

    auto issue = [&](int t, int p) {
        int kp0 = t * 16;
        #pragma unroll
        for (int i = 0; i < 4; i++) {
            int idx = tid + i * 256, r = idx >> 3, c2 = (idx & 7) * 2;
            cp16(&Asb[p*GA_STAGE + r*APG + c2],
                 &A[(size_t)(row0 + r) * Kp2 + kp0 + c2]);
        }
        int r = tid >> 4, c4 = (tid & 15) * 4;
        cp16(&Bsb[p*GB_STAGE + r*BPN + c4],
             &Bp[(size_t)(kp0 + r) * Nc + col0 + c4]);
    };

    issue(0, 0); CP_COMMIT();
    if (T > 1) { issue(1, 1); CP_COMMIT(); }

    for (int t = 0; t < T; t++) {
        const int p = t & 1;
        if (t + 1 < T) cp_wait<1>(); else cp_wait<0>();
        __syncthreads();
        const uint2*    As = Asb + p * GA_STAGE;
        const unsigned* Bs = Bsb + p * GB_STAGE;

        #pragma unroll
        for (int ks = 0; ks < 2; ks++) {
            unsigned ah[2][4], al[2][4];
            #pragma unroll
            for (int mt = 0; mt < 2; mt++) {
                int rbl = wm * 32 + mt * 16;
                uint2 tq;
                tq = As[(rbl + g    ) * APG + ks*8 + c    ]; ah[mt][0]=tq.x; al[mt][0]=tq.y;
                tq = As[(rbl + g + 8) * APG + ks*8 + c    ]; ah[mt][1]=tq.x; al[mt][1]=tq.y;
                tq = As[(rbl + g    ) * APG + ks*8 + c + 4]; ah[mt][2]=tq.x; al[mt][2]=tq.y;
                tq = As[(rbl + g + 8) * APG + ks*8 + c + 4]; ah[mt][3]=tq.x; al[mt][3]=tq.y;
            }
            #pragma unroll
            for (int nt = 0; nt < 4; nt++) {
                int n = wn * 32 + nt * 8 + g;
                unsigned bb[2] = { Bs[(ks*8 + c    ) * BPN + n],
                                   Bs[(ks*8 + c + 4) * BPN + n] };
                mma2h(acc[0][nt], ah[0], al[0], bb);
                mma2h(acc[1][nt], ah[1], al[1], bb);
            }
        }
        __syncthreads();
        if (t + 2 < T) { issue(t + 2, p); CP_COMMIT(); }
    }

    #pragma unroll
    for (int mt = 0; mt < 2; mt++)
        #pragma unroll
        for (int nt = 0; nt < 4; nt++) {
            int r  = row0 + wm * 32 + mt * 16 + g;
            int cc = col0 + wn * 32 + nt * 8 + 2 * c;
            float b0 = bias ? bias[cc] : 0.f, b1 = bias ? bias[cc + 1] : 0.f;
            *(float2*)&Cout[(size_t)r * Nc + cc] =
                make_float2(acc[mt][nt][0] + b0, acc[mt][nt][1] + b1);
            *(float2*)&Cout[(size_t)(r + 8) * Nc + cc] =
                make_float2(acc[mt][nt][2] + b0, acc[mt][nt][3] + b1);
        }
}

// ---------------------------------------------------------------------------
// Flash attention: pre-converted K/V, Q frags pre-split in smem, cp.async
// 2-stage K/V pipeline, 2 CTAs/SM. Block = (bh, 128 Q rows), 256 thr.
// ---------------------------------------------------------------------------
#define KP  36                      // Ks pitch (uint2), ==4 mod 16
#define VPN 72                      // Vs pitch (unsigned), ==8 mod 32
#define QFP 36                      // Qf pitch (uint2), ==4 mod 16
#define AK_STAGE (64*KP)            // uint2
#define AV_STAGE (32*VPN)           // unsigned
#define QF_BYTES (128*QFP*8)        // 36864
#define ST_BYTES (2*AK_STAGE*8 + 2*AV_STAGE*4)  // 55296
#define ATTN_SMEM (QF_BYTES + ST_BYTES)         // 92160 B
#define QSP 68                      // Q fp32 staging pitch (aliases stages)

__global__ __launch_bounds__(256, 2)
void attn_cp(const float* __restrict__ qkv, uint2* __restrict__ Op)
{
    extern __shared__ char dsm[];
    uint2*    Qf  = (uint2*)dsm;                        // [128][QFP] {hi,lo}
    uint2*    Ksb = (uint2*)(dsm + QF_BYTES);
    unsigned* Vsb = (unsigned*)(dsm + QF_BYTES + 2*AK_STAGE*8);
    float*    qstage = (float*)(dsm + QF_BYTES);        // aliases stages

    const int tid = threadIdx.x, lane = tid & 31, warp = tid >> 5;
    const int g = lane >> 2, c = lane & 3;
    const int rb = warp * 16;
    const int bh = blockIdx.y, b = bh >> 3, h = bh & 7;
    const int q0 = blockIdx.x * 128;
    const float* qb = qkv + (size_t)b * N_ * F3 + h * 64;
    const uint2* kpb = g_kp + (size_t)bh * N_ * 32;
    const unsigned* vpb = g_vp + (size_t)bh * 65536;

    // ---- prologue: stage Q (scaled) -> split frags -> Qf
    #pragma unroll
    for (int i = 0; i < 8; i++) {
        int idx = tid + i * 256;
        int r = idx >> 4, c4 = (idx & 15) * 4;
        float4 v = *(const float4*)&qb[(size_t)(q0 + r) * F3 + c4];
        v.x *= SCALE; v.y *= SCALE; v.z *= SCALE; v.w *= SCALE;
        *(float4*)&qstage[r * QSP + c4] = v;
    }
    __syncthreads();
    #pragma unroll
    for (int ks = 0; ks < 4; ks++) {
        float2 t0 = *(const float2*)&qstage[(rb + g    ) * QSP + ks*16 + 2*c    ];
        float2 t1 = *(const float2*)&qstage[(rb + g + 8) * QSP + ks*16 + 2*c    ];
        float2 t2 = *(const float2*)&qstage[(rb + g    ) * QSP + ks*16 + 2*c + 8];
        float2 t3 = *(const float2*)&qstage[(rb + g + 8) * QSP + ks*16 + 2*c + 8];
        unsigned hh, ll;
        split2b(t0.x, t0.y, hh, ll); Qf[(rb + g    ) * QFP + ks*8 + c    ] = make_uint2(hh, ll);
        split2b(t1.x, t1.y, hh, ll); Qf[(rb + g + 8) * QFP + ks*8 + c    ] = make_uint2(hh, ll);
        split2b(t2.x, t2.y, hh, ll); Qf[(rb + g    ) * QFP + ks*8 + c + 4] = make_uint2(hh, ll);
        split2b(t3.x, t3.y, hh, ll); Qf[(rb + g + 8) * QFP + ks*8 + c + 4] = make_uint2(hh, ll);
    }
    __syncthreads();   // all qstage reads done before cp.async overwrites it

    auto issue = [&](int t, int p) {
        #pragma unroll
        for (int i = 0; i < 4; i++) {
            int idx = tid + i * 256, r = idx >> 4, c2 = (idx & 15) * 2;
            cp16(&Ksb[p*AK_STAGE + r*KP + c2], &kpb[(size_t)(t*64 + r) * 32 + c2]);
        }
        #pragma unroll
        for (int i = 0; i < 2; i++) {
            int idx = tid + i * 256, r = idx >> 4, c4 = (idx & 15) * 4;
            cp16(&Vsb[p*AV_STAGE + r*VPN + c4], &vpb[(size_t)(t*32 + r) * 64 + c4]);
        }
    };

    issue(0, 0); CP_COMMIT();
    issue(1, 1); CP_COMMIT();

    float m0 = -INFINITY, m1 = -INFINITY, l0 = 0.f, l1 = 0.f;
    float acc[8][4] = {};

    for (int t = 0; t < 32; t++) {
        const int p = t & 1;
        if (t < 31) cp_wait<1>(); else cp_wait<0>();
        __syncthreads();
        const uint2*    Ks = Ksb + p * AK_STAGE;
        const unsigned* Vs = Vsb + p * AV_STAGE;

        // ---- S = Q @ K^T (3xBF16)
        float sf[8][4] = {};
        #pragma unroll
        for (int ks = 0; ks < 4; ks++) {
            uint2 a0 = Qf[(rb + g    ) * QFP + ks*8 + c    ];
            uint2 a1 = Qf[(rb + g + 8) * QFP + ks*8 + c    ];
            uint2 a2 = Qf[(rb + g    ) * QFP + ks*8 + c + 4];
            uint2 a3 = Qf[(rb + g + 8) * QFP + ks*8 + c + 4];
            unsigned qh[4] = {a0.x, a1.x, a2.x, a3.x};
            unsigned ql[4] = {a0.y, a1.y, a2.y, a3.y};
            #pragma unroll
            for (int nt = 0; nt < 8; nt++) {
                uint2 t0 = Ks[(nt*8 + g) * KP + ks*8 + c    ];
                uint2 t1 = Ks[(nt*8 + g) * KP + ks*8 + c + 4];
                unsigned bh2[2] = {t0.x, t1.x}, bl2[2] = {t0.y, t1.y};
                mma3b(sf[nt], qh, ql, bh2, bl2);
            }
        }

        // ---- online softmax
        float mx0 = -INFINITY, mx1 = -INFINITY;
        #pragma unroll
        for (int nt = 0; nt < 8; nt++) {
            mx0 = fmaxf(mx0, fmaxf(sf[nt][0], sf[nt][1]));
            mx1 = fmaxf(mx1, fmaxf(sf[nt][2], sf[nt][3]));
        }
        mx0 = fmaxf(mx0, __shfl_xor_sync(~0u, mx0, 1));
        mx0 = fmaxf(mx0, __shfl_xor_sync(~0u, mx0, 2));
        mx1 = fmaxf(mx1, __shfl_xor_sync(~0u, mx1, 1));
        mx1 = fmaxf(mx1, __shfl_xor_sync(~0u, mx1, 2));
        float m0n = fmaxf(m0, mx0), m1n = fmaxf(m1, mx1);
        float al0 = __expf(m0 - m0n), al1 = __expf(m1 - m1n);
        float s0 = 0.f, s1 = 0.f;
        #pragma unroll
        for (int nt = 0; nt < 8; nt++) {
            sf[nt][0] = __expf(sf[nt][0] - m0n);
            sf[nt][1] = __expf(sf[nt][1] - m0n);
            sf[nt][2] = __expf(sf[nt][2] - m1n);
            sf[nt][3] = __expf(sf[nt][3] - m1n);
            s0 += sf[nt][0] + sf[nt][1];
            s1 += sf[nt][2] + sf[nt][3];
        }
        s0 += __shfl_xor_sync(~0u, s0, 1); s0 += __shfl_xor_sync(~0u, s0, 2);
        s1 += __shfl_xor_sync(~0u, s1, 1); s1 += __shfl_xor_sync(~0u, s1, 2);
        l0 = l0 * al0 + s0;  l1 = l1 * al1 + s1;
        m0 = m0n;            m1 = m1n;
        #pragma unroll
        for (int nt = 0; nt < 8; nt++) {
            acc[nt][0] *= al0; acc[nt][1] *= al0;
            acc[nt][2] *= al1; acc[nt][3] *= al1;
        }

        // ---- O += P @ V (2xFP16, P split in-register)
        #pragma unroll
        for (int ks = 0; ks < 4; ks++) {
            unsigned pah[4], pal[4];
            split2h(sf[2*ks  ][0], sf[2*ks  ][1], pah[0], pal[0]);
            split2h(sf[2*ks  ][2], sf[2*ks  ][3], pah[1], pal[1]);
            split2h(sf[2*ks+1][0], sf[2*ks+1][1], pah[2], pal[2]);
            split2h(sf[2*ks+1][2], sf[2*ks+1][3], pah[3], pal[3]);
            #pragma unroll
            for (int nt = 0; nt < 8; nt++) {
                unsigned bb[2] = { Vs[(ks*8 + c    ) * VPN + nt*8 + g],
                                   Vs[(ks*8 + c + 4) * VPN + nt*8 + g] };
                mma2h(acc[nt], pah, pal, bb);
            }
        }

        __syncthreads();
        if (t + 2 < 32) { issue(t + 2, p); CP_COMMIT(); }
    }

    // ---- epilogue: /l, write pre-split fp16 pairs (= proj A operand)
    float i0 = 1.f / l0, i1 = 1.f / l1;
    size_t f0 = ((size_t)bh * N_ + q0 + rb + g    ) * 64;
    size_t f1 = ((size_t)bh * N_ + q0 + rb + g + 8) * 64;
    #pragma unroll
    for (int nt = 0; nt < 8; nt++) {
        int cc = nt * 8 + 2 * c;
        unsigned hh, ll;
        split2h(acc[nt][0] * i0, acc[nt][1] * i0, hh, ll);
        Op[(f0 + cc) >> 1] = make_uint2(hh, ll);
        split2h(acc[nt][2] * i1, acc[nt][3] * i1, hh, ll);
        Op[(f1 + cc) >> 1] = make_uint2(hh, ll);
    }
}

// ---------------------------------------------------------------------------
extern "C" void kernel_launch(void* const* d_in, const int* in_sizes, int n_in,
                              void* d_out, int out_size)
{
    const float* x      = (const float*)d_in[0];
    const float* qkv_w  = (const float*)d_in[1];
    const float* proj_w = (const float*)d_in[2];
    const float* proj_b = (const float*)d_in[3];
    float* out = (float*)d_out;

    float *qkv_p;  uint2 *xs_p, *op_p;  unsigned *wq_p, *wp_p;
    cudaGetSymbolAddress((void**)&qkv_p, g_qkv);
    cudaGetSymbolAddress((void**)&xs_p,  g_xs);
    cudaGetSymbolAddress((void**)&wq_p,  g_wq);
    cudaGetSymbolAddress((void**)&wp_p,  g_wp);
    cudaGetSymbolAddress((void**)&op_p,  g_op);

    cudaFuncSetAttribute(gemm_cp, cudaFuncAttributeMaxDynamicSharedMemorySize, GEMM_SMEM);
    cudaFuncSetAttribute(attn_cp, cudaFuncAttributeMaxDynamicSharedMemorySize, ATTN_SMEM);

    // 0) pre-split x + pack weights
    prep_static<<<1536, 256>>>(x, qkv_w, proj_w);

    // 1) QKV projection: (4096x512) @ (512x1536)
    dim3 g1(F3 / 64, 4096 / 128);
    gemm_cp<<<g1, 256, GEMM_SMEM>>>(xs_p, wq_p, nullptr, qkv_p, 4096, F3, C_);

    // 2) pre-convert K (bf16 split) and V (fp16 pairs)
    prep_kv<<<2048, 256>>>();

    // 3) flash attention -> pre-split O
    dim3 g2(N_ / 128, B_ * H_);
    attn_cp<<<g2, 256, ATTN_SMEM>>>(qkv_p, op_p);

    // 4) output projection: (4096x512) @ (512x512) + bias
    dim3 g3(C_ / 64, 4096 / 128);
    gemm_cp<<<g3, 256, GEMM_SMEM>>>(op_p, wp_p, proj_b, out, 4096, C_, C_);
}